// round 13
// baseline (speedup 1.0000x reference)
#include <cuda_runtime.h>
#include <cuda_bf16.h>
#include <stdint.h>
#include <math.h>

typedef unsigned int u32;

// ---------------- problem constants ----------------
#define BB 8
#define TT 1024
#define CIN 55
#define DD 512
#define LL 3
#define SEQW 10
#define TRR 512
#define TU 512

// ---------------- fp32 scratch ----------------
__device__ float g_pe[TT * DD];
__device__ float g_ex[BB * TT * DD];
__device__ float g_xe[BB * TU * DD];
__device__ float g_v [BB * TT * DD];
__device__ float g_att[BB * TU * TU];
__device__ float g_t1[BB * TT * DD];
__device__ float g_tok[BB * TT * DD];
__device__ float g_score[BB * TT];
__device__ int   g_flag[BB * TT];
__device__ int   g_upos[BB * TT];
__device__ int   g_ulist[BB * TU];

// ---------------- bf16 hi/lo scratch ----------------
#define NXE (BB * TT * DD)
__device__ __nv_bfloat16 g_XH[NXE], g_XL[NXE];
__device__ __nv_bfloat16 g_QH[NXE], g_QL[NXE];
__device__ __nv_bfloat16 g_KH[NXE], g_KL[NXE];
__device__ __nv_bfloat16 g_SH[BB*TT*TT], g_SL[BB*TT*TT];
__device__ __nv_bfloat16 g_VH[NXE], g_VL[NXE];
__device__ __nv_bfloat16 g_TH[NXE], g_TL[NXE];
#define NW 6815744   // all weights pre-split: 2x(3x1536x512) + 2x(3x512x512) + 2x(512x512)
__device__ __nv_bfloat16 g_WH[NW], g_WL[NW];

// ---------------- PE ----------------
__global__ void pe_kernel() {
    int t = blockIdx.x;
    int i = threadIdx.x;
    float divv = expf((float)(2 * i) * (-9.210340371976184f / (float)DD));
    float ang = (float)t * divv;
    g_pe[t * DD + 2 * i]     = sinf(ang);
    g_pe[t * DD + 2 * i + 1] = cosf(ang);
}

// ---------------- embedding ----------------
__global__ void embed_kernel(const float* __restrict__ x, const float* __restrict__ cw,
                             float* __restrict__ ex) {
    int t = blockIdx.x, b = blockIdx.y;
    __shared__ float sw[CIN * 3];
    int tid = threadIdx.x;
    for (int i = tid; i < CIN * 3; i += 128) {
        int c = i / 3, k = i % 3;
        int tt = t + k - 1;
        if (tt < 0) tt += TT;
        if (tt >= TT) tt -= TT;
        sw[i] = x[((long long)b * TT + tt) * CIN + c];
    }
    __syncthreads();
#pragma unroll
    for (int p = 0; p < 4; p++) {
        int d = tid + p * 128;
        const float* w = cw + (long long)d * (CIN * 3);
        float acc = 0.f;
#pragma unroll 15
        for (int i = 0; i < CIN * 3; i++) acc = fmaf(sw[i], w[i], acc);
        ex[((long long)b * TT + t) * DD + d] = acc + g_pe[t * DD + d];
    }
}

// ---------------- score ----------------
__global__ void score_kernel(const float* __restrict__ ex, float* __restrict__ score) {
    int t = blockIdx.x, b = blockIdx.y;
    int lo = t - (SEQW - 1); if (lo < 0) lo = 0;
    float inv = 1.f / (float)(t + 1 - lo);
    int tid = threadIdx.x;
    float vs = 0.f, ms = 0.f;
#pragma unroll
    for (int p = 0; p < 2; p++) {
        int d = tid + p * 256;
        float s1 = 0.f, s2 = 0.f;
        for (int w = lo; w <= t; w++) {
            float v = ex[((long long)b * TT + w) * DD + d];
            s1 += v; s2 += v * v;
        }
        float m = s1 * inv, m2 = s2 * inv;
        vs += m2 - m * m;
        ms += m;
    }
    __shared__ float rv[256], rm[256];
    rv[tid] = vs; rm[tid] = ms; __syncthreads();
    for (int s = 128; s > 0; s >>= 1) {
        if (tid < s) { rv[tid] += rv[tid + s]; rm[tid] += rm[tid + s]; }
        __syncthreads();
    }
    if (tid == 0) score[b * TT + t] = rv[0] / rm[0];
}

// ---------------- selection ----------------
__global__ void select_kernel() {
    int b = blockIdx.x;
    int t = threadIdx.x;
    __shared__ float ss[TT];
    __shared__ int   sf[TT];
    float myv = g_score[b * TT + t];
    ss[t] = myv;
    __syncthreads();
    int rank = 0;
    for (int i = 0; i < TT; i++) {
        float o = ss[i];
        rank += (o > myv) || (o == myv && i < t);
    }
    int masked = (rank < TRR) ? 1 : 0;
    sf[t] = masked;
    __syncthreads();
    int ucnt = 0;
    for (int i = 0; i < t; i++) ucnt += (sf[i] == 0);
    g_flag[b * TT + t] = masked;
    if (!masked) {
        g_upos[b * TT + t] = ucnt;
        g_ulist[b * TU + ucnt] = t;
    } else {
        g_upos[b * TT + t] = -1;
    }
}

// ---------------- split helpers ----------------
__device__ __forceinline__ void writeHL2(__nv_bfloat16* H, __nv_bfloat16* L,
                                         long long idx, float v0, float v1) {
    __nv_bfloat16 h0 = __float2bfloat16(v0), h1 = __float2bfloat16(v1);
    __nv_bfloat162 hh = __halves2bfloat162(h0, h1);
    __nv_bfloat162 ll = __floats2bfloat162_rn(v0 - __bfloat162float(h0),
                                              v1 - __bfloat162float(h1));
    *(__nv_bfloat162*)(H + idx) = hh;
    *(__nv_bfloat162*)(L + idx) = ll;
}
__device__ __forceinline__ void writeHL1(__nv_bfloat16* H, __nv_bfloat16* L,
                                         long long idx, float v) {
    __nv_bfloat16 h = __float2bfloat16(v);
    H[idx] = h;
    L[idx] = __float2bfloat16(v - __bfloat162float(h));
}

// ---------------- gather (+ hi/lo) ----------------
__global__ void gather_kernel(const float* __restrict__ ex, float* __restrict__ xe,
                              __nv_bfloat16* __restrict__ XH, __nv_bfloat16* __restrict__ XL) {
    int p = blockIdx.x, b = blockIdx.y;
    int t = g_ulist[b * TU + p];
    const float* src = ex + ((long long)b * TT + t) * DD;
    long long o = ((long long)b * TU + p) * DD;
    for (int d = threadIdx.x; d < DD; d += 256) {
        float v = src[d];
        xe[o + d] = v;
        writeHL1(XH, XL, o + d, v);
    }
}

// ---------------- decoder tokens (+ hi/lo) ----------------
__global__ void tokens_kernel(const float* __restrict__ ux, const float* __restrict__ mtk,
                              float* __restrict__ tok,
                              __nv_bfloat16* __restrict__ XH, __nv_bfloat16* __restrict__ XL) {
    int t = blockIdx.x, b = blockIdx.y;
    long long o = ((long long)b * TT + t) * DD;
    if (g_flag[b * TT + t]) {
        for (int d = threadIdx.x; d < DD; d += 256) {
            float v = mtk[d] + g_pe[t * DD + d];
            tok[o + d] = v;
            writeHL1(XH, XL, o + d, v);
        }
    } else {
        int p = g_upos[b * TT + t];
        const float* src = ux + ((long long)b * TT * 0 + (long long)b * TU + p) * DD;
        for (int d = threadIdx.x; d < DD; d += 256) {
            float v = src[d];
            tok[o + d] = v;
            writeHL1(XH, XL, o + d, v);
        }
    }
}

// ---------------- transpose-split with strides ----------------
// X: batch b at X + b*sIn, [R][C] fp32 -> H,L at + b*sOut, [C][R] bf16
__global__ void tsplit_kernel(const float* __restrict__ X, __nv_bfloat16* __restrict__ H,
                              __nv_bfloat16* __restrict__ L, int R, int C,
                              long long sIn, long long sOut) {
    __shared__ float tile[32][33];
    int b = blockIdx.z;
    int c0 = blockIdx.x * 32, r0 = blockIdx.y * 32;
    const float* Xb = X + (long long)b * sIn;
    int tx = threadIdx.x, ty = threadIdx.y;
#pragma unroll
    for (int i = ty; i < 32; i += 8)
        tile[i][tx] = Xb[(long long)(r0 + i) * C + c0 + tx];
    __syncthreads();
    long long ob = (long long)b * sOut;
#pragma unroll
    for (int i = ty; i < 32; i += 8) {
        float v = tile[tx][i];
        writeHL1(H, L, ob + (long long)(c0 + i) * R + r0 + tx, v);
    }
}

// ================= tensor-core GEMM on pre-split bf16 =================
// modes: 0 fp32(+bias)(+resid); 1 gelu->C; 2 sigmoid->C; 3 HL; 4 fp32+HL;
//        5 QKV merged (q->Oh/Ol+bias, k->Oh2/Ol2+bias2, v->C+bias3; row stride 512);
//        6 gelu->HL
// 2-stage cp.async, 8 warps, warp tile 64x32 — exact R5 loop structure.

#define RSTR 40
#define PARTB (128 * RSTR * 2)
#define STAGEB (4 * PARTB)

__device__ __forceinline__ void cpa(u32 dst, const void* src) {
    asm volatile("cp.async.cg.shared.global [%0], [%1], 16;\n" :: "r"(dst), "l"(src));
}
__device__ __forceinline__ void ldsm4(u32* r, u32 addr) {
    asm volatile("ldmatrix.sync.aligned.m8n8.x4.shared.b16 {%0,%1,%2,%3}, [%4];\n"
        : "=r"(r[0]), "=r"(r[1]), "=r"(r[2]), "=r"(r[3]) : "r"(addr));
}
__device__ __forceinline__ void mma16816(float* d, const u32* a, u32 b0, u32 b1) {
    asm volatile(
        "mma.sync.aligned.m16n8k16.row.col.f32.bf16.bf16.f32 "
        "{%0,%1,%2,%3}, {%4,%5,%6,%7}, {%8,%9}, {%0,%1,%2,%3};\n"
        : "+f"(d[0]), "+f"(d[1]), "+f"(d[2]), "+f"(d[3])
        : "r"(a[0]), "r"(a[1]), "r"(a[2]), "r"(a[3]), "r"(b0), "r"(b1));
}

__device__ __forceinline__ void load_stage(
    u32 sbase, const __nv_bfloat16* Ah, const __nv_bfloat16* Al,
    const __nv_bfloat16* Bh, const __nv_bfloat16* Bl,
    int m0, int n0, int K, int k0, int tid) {
    int r = tid >> 2, c = tid & 3;
    u32 off1 = (u32)(r * RSTR + c * 8) * 2;
    u32 off2 = (u32)((r + 64) * RSTR + c * 8) * 2;
    long long a1 = (long long)(m0 + r) * K + k0 + c * 8;
    long long a2 = a1 + (long long)64 * K;
    long long b1 = (long long)(n0 + r) * K + k0 + c * 8;
    long long b2 = b1 + (long long)64 * K;
    cpa(sbase + off1, Ah + a1);               cpa(sbase + off2, Ah + a2);
    cpa(sbase + PARTB + off1, Al + a1);       cpa(sbase + PARTB + off2, Al + a2);
    cpa(sbase + 2*PARTB + off1, Bh + b1);     cpa(sbase + 2*PARTB + off2, Bh + b2);
    cpa(sbase + 3*PARTB + off1, Bl + b1);     cpa(sbase + 3*PARTB + off2, Bl + b2);
    asm volatile("cp.async.commit_group;\n");
}

__global__ __launch_bounds__(256)
void gemm3_kernel(const __nv_bfloat16* __restrict__ Ah, const __nv_bfloat16* __restrict__ Al,
                  const __nv_bfloat16* __restrict__ Bh, const __nv_bfloat16* __restrict__ Bl,
                  const float* __restrict__ bias, const float* __restrict__ bias2,
                  const float* __restrict__ bias3,
                  const float* __restrict__ resid, float* __restrict__ C,
                  __nv_bfloat16* __restrict__ Oh, __nv_bfloat16* __restrict__ Ol,
                  __nv_bfloat16* __restrict__ Oh2, __nv_bfloat16* __restrict__ Ol2,
                  int M, int N, int K,
                  long long sA, long long sB, long long sC,
                  float alpha, int mode) {
    extern __shared__ __nv_bfloat16 smraw[];
    u32 smb = (u32)__cvta_generic_to_shared(smraw);

    int bz = blockIdx.z;
    Ah += (long long)bz * sA; Al += (long long)bz * sA;
    Bh += (long long)bz * sB; Bl += (long long)bz * sB;
    C  += (long long)bz * sC;
    const float* R = resid ? resid + (long long)bz * sC : nullptr;

    int m0 = blockIdx.y * 128, n0 = blockIdx.x * 128;
    int tid = threadIdx.x, lane = tid & 31, wid = tid >> 5;
    int wm = (wid & 1) * 64, wn = (wid >> 1) * 32;
    int g = lane >> 2, t4 = lane & 3;

    float acc[4][4][4];
#pragma unroll
    for (int i = 0; i < 4; i++)
#pragma unroll
        for (int j = 0; j < 4; j++)
#pragma unroll
            for (int q = 0; q < 4; q++) acc[i][j][q] = 0.f;

    int nk = K / 32;
    load_stage(smb, Ah, Al, Bh, Bl, m0, n0, K, 0, tid);
    load_stage(smb + STAGEB, Ah, Al, Bh, Bl, m0, n0, K, 32, tid);

    int arow = lane & 15;
    int achkbase = lane >> 4;
    int brow = (lane & 7) + ((lane & 16) >> 1);
    int bchkbase = (lane >> 3) & 1;

    for (int kt = 0; kt < nk; kt++) {
        asm volatile("cp.async.wait_group 1;\n");
        __syncthreads();
        u32 base = smb + (kt & 1) * STAGEB;
        u32 aH = base, aL = base + PARTB, bH = base + 2*PARTB, bL = base + 3*PARTB;
#pragma unroll
        for (int kq = 0; kq < 2; kq++) {
            u32 ah[4][4], al[4][4];
            int achk = kq * 2 + achkbase;
#pragma unroll
            for (int mf = 0; mf < 4; mf++) {
                u32 off = (u32)((wm + mf * 16 + arow) * RSTR + achk * 8) * 2;
                ldsm4(ah[mf], aH + off);
                ldsm4(al[mf], aL + off);
            }
            int bchk = kq * 2 + bchkbase;
#pragma unroll
            for (int np = 0; np < 2; np++) {
                u32 off = (u32)((wn + np * 16 + brow) * RSTR + bchk * 8) * 2;
                u32 bh[4], bl[4];
                ldsm4(bh, bH + off);
                ldsm4(bl, bL + off);
#pragma unroll
                for (int ni = 0; ni < 2; ni++) {
                    int nf = np * 2 + ni;
                    u32 b0h = bh[ni*2], b1h = bh[ni*2+1];
                    u32 b0l = bl[ni*2], b1l = bl[ni*2+1];
#pragma unroll
                    for (int mf = 0; mf < 4; mf++) {
                        mma16816(acc[mf][nf], ah[mf], b0h, b1h);
                        mma16816(acc[mf][nf], ah[mf], b0l, b1l);
                        mma16816(acc[mf][nf], al[mf], b0h, b1h);
                    }
                }
            }
        }
        __syncthreads();
        if (kt + 2 < nk)
            load_stage(smb + (kt & 1) * STAGEB, Ah, Al, Bh, Bl, m0, n0, K, (kt + 2) * 32, tid);
        else
            asm volatile("cp.async.commit_group;\n");
    }

    // ---- epilogue ----
#pragma unroll
    for (int mf = 0; mf < 4; mf++) {
        int r0 = m0 + wm + mf * 16 + g;
#pragma unroll
        for (int nf = 0; nf < 4; nf++) {
            int cc = n0 + wn + nf * 8 + t4 * 2;
#pragma unroll
            for (int half = 0; half < 2; half++) {
                int r = r0 + half * 8;
                float v0 = acc[mf][nf][half * 2 + 0] * alpha;
                float v1 = acc[mf][nf][half * 2 + 1] * alpha;
                if (mode == 5) {
                    int reg = cc >> 9, lc = cc & 511;
                    long long idx = (long long)r * 512 + lc;
                    if (reg == 0) {
                        v0 += bias[lc]; v1 += bias[lc + 1];
                        writeHL2(Oh, Ol, idx, v0, v1);
                    } else if (reg == 1) {
                        v0 += bias2[lc]; v1 += bias2[lc + 1];
                        writeHL2(Oh2, Ol2, idx, v0, v1);
                    } else {
                        v0 += bias3[lc]; v1 += bias3[lc + 1];
                        *(float2*)(C + idx) = make_float2(v0, v1);
                    }
                } else {
                    if (bias) { v0 += bias[cc]; v1 += bias[cc + 1]; }
                    if (R) {
                        v0 += R[(long long)r * N + cc];
                        v1 += R[(long long)r * N + cc + 1];
                    }
                    if (mode == 1 || mode == 6) {
                        v0 = 0.5f * v0 * (1.f + erff(v0 * 0.7071067811865475f));
                        v1 = 0.5f * v1 * (1.f + erff(v1 * 0.7071067811865475f));
                    } else if (mode == 2) {
                        v0 = 1.f / (1.f + __expf(-v0));
                        v1 = 1.f / (1.f + __expf(-v1));
                    }
                    long long idx = (long long)r * N + cc;
                    if (mode <= 2 || mode == 4)
                        *(float2*)(C + idx) = make_float2(v0, v1);
                    if (mode == 3 || mode == 4 || mode == 6)
                        writeHL2(Oh, Ol, idx, v0, v1);
                }
            }
        }
    }
}

// ---------------- softmax (+ hi/lo emit) ----------------
__global__ void softmax_split_kernel(float* __restrict__ S,
                                     __nv_bfloat16* __restrict__ H,
                                     __nv_bfloat16* __restrict__ L, int Nc) {
    long long row = blockIdx.x;
    float* p = S + row * Nc;
    __shared__ float red[256];
    int tid = threadIdx.x;
    float mx = -1e30f;
    for (int i = tid; i < Nc; i += 256) mx = fmaxf(mx, p[i]);
    red[tid] = mx; __syncthreads();
    for (int s = 128; s > 0; s >>= 1) { if (tid < s) red[tid] = fmaxf(red[tid], red[tid + s]); __syncthreads(); }
    mx = red[0]; __syncthreads();
    float sum = 0.f;
    for (int i = tid; i < Nc; i += 256) { float e = __expf(p[i] - mx); p[i] = e; sum += e; }
    red[tid] = sum; __syncthreads();
    for (int s = 128; s > 0; s >>= 1) { if (tid < s) red[tid] += red[tid + s]; __syncthreads(); }
    float inv = 1.f / red[0];
    long long ro = row * Nc;
    for (int i = tid; i < Nc; i += 256) {
        float e = p[i] * inv;
        p[i] = e;
        writeHL1(H, L, ro + i, e);
    }
}

// ---------------- layer norm -> fp32 ----------------
__global__ void ln_kernel(const float* __restrict__ X, const float* __restrict__ g,
                          const float* __restrict__ b, float* __restrict__ Y) {
    long long row = blockIdx.x;
    const float* x = X + row * DD;
    float* y = Y + row * DD;
    __shared__ float red[256];
    int tid = threadIdx.x;
    float v0 = x[tid], v1 = x[tid + 256];
    red[tid] = v0 + v1; __syncthreads();
    for (int s = 128; s > 0; s >>= 1) { if (tid < s) red[tid] += red[tid + s]; __syncthreads(); }
    float mu = red[0] * (1.f / (float)DD); __syncthreads();
    float d0 = v0 - mu, d1 = v1 - mu;
    red[tid] = d0 * d0 + d1 * d1; __syncthreads();
    for (int s = 128; s > 0; s >>= 1) { if (tid < s) red[tid] += red[tid + s]; __syncthreads(); }
    float inv = rsqrtf(red[0] * (1.f / (float)DD) + 1e-5f);
    y[tid]       = d0 * inv * g[tid] + b[tid];
    y[tid + 256] = d1 * inv * g[tid + 256] + b[tid + 256];
}

// ---------------- layer norm -> hi/lo ----------------
__global__ void ln_split_kernel(const float* __restrict__ X, const float* __restrict__ g,
                                const float* __restrict__ b,
                                __nv_bfloat16* __restrict__ H, __nv_bfloat16* __restrict__ L) {
    long long row = blockIdx.x;
    const float* x = X + row * DD;
    __shared__ float red[256];
    int tid = threadIdx.x;
    float v0 = x[tid], v1 = x[tid + 256];
    red[tid] = v0 + v1; __syncthreads();
    for (int s = 128; s > 0; s >>= 1) { if (tid < s) red[tid] += red[tid + s]; __syncthreads(); }
    float mu = red[0] * (1.f / (float)DD); __syncthreads();
    float d0 = v0 - mu, d1 = v1 - mu;
    red[tid] = d0 * d0 + d1 * d1; __syncthreads();
    for (int s = 128; s > 0; s >>= 1) { if (tid < s) red[tid] += red[tid + s]; __syncthreads(); }
    float inv = rsqrtf(red[0] * (1.f / (float)DD) + 1e-5f);
    long long ro = row * DD;
    writeHL1(H, L, ro + tid,       d0 * inv * g[tid] + b[tid]);
    writeHL1(H, L, ro + tid + 256, d1 * inv * g[tid + 256] + b[tid + 256]);
}

// ---------------- host orchestration ----------------
extern "C" void kernel_launch(void* const* d_in, const int* in_sizes, int n_in,
                              void* d_out, int out_size) {
    float *ex, *xe, *v, *att, *t1, *tok, *score;
    cudaGetSymbolAddress((void**)&ex,  g_ex);
    cudaGetSymbolAddress((void**)&xe,  g_xe);
    cudaGetSymbolAddress((void**)&v,   g_v);
    cudaGetSymbolAddress((void**)&att, g_att);
    cudaGetSymbolAddress((void**)&t1,  g_t1);
    cudaGetSymbolAddress((void**)&tok, g_tok);
    cudaGetSymbolAddress((void**)&score, g_score);
    __nv_bfloat16 *XH,*XL,*QH,*QL,*KH,*KL,*SH,*SL,*VH,*VL,*TH,*TL,*WH,*WL;
    cudaGetSymbolAddress((void**)&XH, g_XH); cudaGetSymbolAddress((void**)&XL, g_XL);
    cudaGetSymbolAddress((void**)&QH, g_QH); cudaGetSymbolAddress((void**)&QL, g_QL);
    cudaGetSymbolAddress((void**)&KH, g_KH); cudaGetSymbolAddress((void**)&KL, g_KL);
    cudaGetSymbolAddress((void**)&SH, g_SH); cudaGetSymbolAddress((void**)&SL, g_SL);
    cudaGetSymbolAddress((void**)&VH, g_VH); cudaGetSymbolAddress((void**)&VL, g_VL);
    cudaGetSymbolAddress((void**)&TH, g_TH); cudaGetSymbolAddress((void**)&TL, g_TL);
    cudaGetSymbolAddress((void**)&WH, g_WH); cudaGetSymbolAddress((void**)&WL, g_WL);

    static int smem_set = 0;
    if (!smem_set) {
        cudaFuncSetAttribute(gemm3_kernel, cudaFuncAttributeMaxDynamicSharedMemorySize,
                             2 * STAGEB);
        smem_set = 1;
    }

    const float* in[31];
    for (int i = 0; i < 31 && i < n_in; i++) in[i] = (const float*)d_in[i];

    const float *x = in[0], *conv_w = in[1], *mask_token = in[2];
    const float *pro_w1, *pro_b1, *pro_w2, *pro_b2;
    const float *eW[4], *eBi[4], *eg, *ebb, *eng, *enb;
    const float *dW[4], *dBi[4], *dg, *dbb, *dng, *dnb;

    bool sig = (in_sizes[3] == LL * DD * DD);
    if (sig) {
        eW[0]=in[3];  eBi[0]=in[4];  eW[1]=in[5];  eBi[1]=in[6];
        eW[2]=in[7];  eBi[2]=in[8];  eW[3]=in[9];  eBi[3]=in[10];
        eg=in[11]; ebb=in[12]; eng=in[13]; enb=in[14];
        dW[0]=in[15]; dBi[0]=in[16]; dW[1]=in[17]; dBi[1]=in[18];
        dW[2]=in[19]; dBi[2]=in[20]; dW[3]=in[21]; dBi[3]=in[22];
        dg=in[23]; dbb=in[24]; dng=in[25]; dnb=in[26];
        pro_w1=in[27]; pro_b1=in[28]; pro_w2=in[29]; pro_b2=in[30];
    } else {
        pro_w1=in[3]; pro_b1=in[4]; pro_w2=in[5]; pro_b2=in[6];
        eW[0]=in[7];  eW[1]=in[8];  eW[2]=in[9];  eW[3]=in[10];
        eBi[0]=in[11]; eBi[1]=in[12]; eBi[2]=in[13]; eBi[3]=in[14];
        eg=in[15]; ebb=in[16]; eng=in[17]; enb=in[18];
        dW[0]=in[19]; dW[1]=in[20]; dW[2]=in[21]; dW[3]=in[22];
        dBi[0]=in[23]; dBi[1]=in[24]; dBi[2]=in[25]; dBi[3]=in[26];
        dg=in[27]; dbb=in[28]; dng=in[29]; dnb=in[30];
    }

    const float SCALE = 0.044194173824159216f;

    // weight layout in WH/WL (elements)
    const long long QKV_E = 1536LL * 512;      // per-layer merged qkv
    const long long WO_E  = 512LL * 512;
    const long long ENCQKV = 0;
    const long long DECQKV = 3 * QKV_E;
    const long long ENCWO  = 6 * QKV_E;
    const long long DECWO  = ENCWO + 3 * WO_E;
    const long long PW1    = DECWO + 3 * WO_E;
    const long long PW2    = PW1 + WO_E;

    auto tsplitS = [&](const float* X, __nv_bfloat16* H, __nv_bfloat16* L,
                       int R, int C, long long sIn, long long sOut, int nb) {
        tsplit_kernel<<<dim3(C / 32, R / 32, nb), dim3(32, 8)>>>(X, H, L, R, C, sIn, sOut);
    };
    auto gemm = [&](const __nv_bfloat16* ah, const __nv_bfloat16* al,
                    const __nv_bfloat16* bh, const __nv_bfloat16* bl,
                    const float* b1, const float* b2, const float* b3,
                    const float* resid, float* C,
                    __nv_bfloat16* oh, __nv_bfloat16* ol,
                    __nv_bfloat16* oh2, __nv_bfloat16* ol2,
                    int M, int N, int K, long long sA, long long sB, long long sC,
                    int nb, float alpha, int mode) {
        dim3 grid(N / 128, M / 128, nb);
        gemm3_kernel<<<grid, 256, 2 * STAGEB>>>(ah, al, bh, bl, b1, b2, b3, resid, C,
                                                oh, ol, oh2, ol2,
                                                M, N, K, sA, sB, sC, alpha, mode);
    };

    // ---- pre-split ALL weights once (off the per-layer critical path) ----
    tsplitS(eW[0], WH + ENCQKV,             WL + ENCQKV,             DD, DD, WO_E, QKV_E, LL);
    tsplitS(eW[1], WH + ENCQKV + 512*512,   WL + ENCQKV + 512*512,   DD, DD, WO_E, QKV_E, LL);
    tsplitS(eW[2], WH + ENCQKV + 1024*512,  WL + ENCQKV + 1024*512,  DD, DD, WO_E, QKV_E, LL);
    tsplitS(eW[3], WH + ENCWO,              WL + ENCWO,              DD, DD, WO_E, WO_E,  LL);
    tsplitS(dW[0], WH + DECQKV,             WL + DECQKV,             DD, DD, WO_E, QKV_E, LL);
    tsplitS(dW[1], WH + DECQKV + 512*512,   WL + DECQKV + 512*512,   DD, DD, WO_E, QKV_E, LL);
    tsplitS(dW[2], WH + DECQKV + 1024*512,  WL + DECQKV + 1024*512,  DD, DD, WO_E, QKV_E, LL);
    tsplitS(dW[3], WH + DECWO,              WL + DECWO,              DD, DD, WO_E, WO_E,  LL);
    tsplitS(pro_w1, WH + PW1, WL + PW1, DD, DD, WO_E, WO_E, 1);
    tsplitS(pro_w2, WH + PW2, WL + PW2, DD, DD, WO_E, WO_E, 1);

    // ---- front end ----
    pe_kernel<<<TT, 256>>>();
    embed_kernel<<<dim3(TT, BB), 128>>>(x, conv_w, ex);
    score_kernel<<<dim3(TT, BB), 256>>>(ex, score);
    select_kernel<<<BB, TT>>>();
    gather_kernel<<<dim3(TU, BB), 256>>>(ex, xe, XH, XL);

    // ---- encoder (Tc = 512) ----
    {
        int Tc = TU, BT = BB * Tc;
        long long sQK = (long long)Tc * DD, sAtt = (long long)Tc * Tc;
        for (int l = 0; l < LL; l++) {
            const float *bq = eBi[0] + l * DD, *bk = eBi[1] + l * DD;
            const float *bv = eBi[2] + l * DD, *bo = eBi[3] + l * DD;
            const __nv_bfloat16 *qkvH = WH + ENCQKV + l * QKV_E;
            const __nv_bfloat16 *qkvL = WL + ENCQKV + l * QKV_E;
            const __nv_bfloat16 *woH  = WH + ENCWO + l * WO_E;
            const __nv_bfloat16 *woL  = WL + ENCWO + l * WO_E;
            gemm(XH, XL, qkvH, qkvL, bq, bk, bv, nullptr, v, QH, QL, KH, KL,
                 BT, 1536, DD, 0, 0, 0, 1, 1.f, 5);
            gemm(QH, QL, KH, KL, nullptr, nullptr, nullptr, nullptr, att,
                 nullptr, nullptr, nullptr, nullptr,
                 Tc, Tc, DD, sQK, sQK, sAtt, BB, SCALE, 0);
            softmax_split_kernel<<<BB * Tc, 256>>>(att, SH, SL, Tc);
            tsplitS(v, VH, VL, Tc, DD, sQK, sQK, BB);
            gemm(SH, SL, VH, VL, nullptr, nullptr, nullptr, xe, t1,
                 nullptr, nullptr, nullptr, nullptr,
                 Tc, DD, Tc, sAtt, sQK, sQK, BB, 1.f, 0);
            ln_split_kernel<<<BT, 256>>>(t1, eg + l * DD, ebb + l * DD, TH, TL);
            gemm(TH, TL, woH, woL, bo, nullptr, nullptr, t1, xe,
                 XH, XL, nullptr, nullptr, BT, DD, DD, 0, 0, 0, 1, 1.f, 4);
        }
        ln_kernel<<<BT, 256>>>(xe, eng, enb, t1);    // ux fp32
    }

    // ---- decoder tokens ----
    tokens_kernel<<<dim3(TT, BB), 256>>>(t1, mask_token, tok, XH, XL);

    // ---- decoder (Tc = 1024), att maps into d_out ----
    {
        int Tc = TT, BT = BB * Tc;
        long long sQK = (long long)Tc * DD, sAtt = (long long)Tc * Tc;
        for (int l = 0; l < LL; l++) {
            const float *bq = dBi[0] + l * DD, *bk = dBi[1] + l * DD;
            const float *bv = dBi[2] + l * DD, *bo = dBi[3] + l * DD;
            const __nv_bfloat16 *qkvH = WH + DECQKV + l * QKV_E;
            const __nv_bfloat16 *qkvL = WL + DECQKV + l * QKV_E;
            const __nv_bfloat16 *woH  = WH + DECWO + l * WO_E;
            const __nv_bfloat16 *woL  = WL + DECWO + l * WO_E;
            float* attOut = (float*)d_out + (long long)l * BB * TT * TT;
            gemm(XH, XL, qkvH, qkvL, bq, bk, bv, nullptr, v, QH, QL, KH, KL,
                 BT, 1536, DD, 0, 0, 0, 1, 1.f, 5);
            gemm(QH, QL, KH, KL, nullptr, nullptr, nullptr, nullptr, attOut,
                 nullptr, nullptr, nullptr, nullptr,
                 Tc, Tc, DD, sQK, sQK, sAtt, BB, SCALE, 0);
            softmax_split_kernel<<<BB * Tc, 256>>>(attOut, SH, SL, Tc);
            tsplitS(v, VH, VL, Tc, DD, sQK, sQK, BB);
            gemm(SH, SL, VH, VL, nullptr, nullptr, nullptr, tok, t1,
                 nullptr, nullptr, nullptr, nullptr,
                 Tc, DD, Tc, sAtt, sQK, sQK, BB, 1.f, 0);
            ln_split_kernel<<<BT, 256>>>(t1, dg + l * DD, dbb + l * DD, TH, TL);
            gemm(TH, TL, woH, woL, bo, nullptr, nullptr, t1, tok,
                 XH, XL, nullptr, nullptr, BT, DD, DD, 0, 0, 0, 1, 1.f, 4);
        }
        ln_split_kernel<<<BB * TT, 256>>>(tok, dng, dnb, TH, TL);

        // ---- projector ----
        float* rec = (float*)d_out + (long long)LL * BB * TT * TT;
        gemm(TH, TL, WH + PW1, WL + PW1, pro_b1, nullptr, nullptr, nullptr, nullptr,
             QH, QL, nullptr, nullptr, BB * TT, DD, DD, 0, 0, 0, 1, 1.f, 6);
        gemm(QH, QL, WH + PW2, WL + PW2, pro_b2, nullptr, nullptr, nullptr, rec,
             nullptr, nullptr, nullptr, nullptr, BB * TT, DD, DD, 0, 0, 0, 1, 1.f, 2);
    }
}

// round 14
// speedup vs baseline: 1.6467x; 1.6467x over previous
#include <cuda_runtime.h>
#include <cuda_bf16.h>
#include <stdint.h>
#include <math.h>

typedef unsigned int u32;

// ---------------- problem constants ----------------
#define BB 8
#define TT 1024
#define CIN 55
#define DD 512
#define LL 3
#define SEQW 10
#define TRR 512          // masked count
#define TU 512           // unmasked count (T - TR)

// ---------------- device scratch ----------------
__device__ float g_pe[TT * DD];
__device__ float g_ex[BB * TT * DD];
__device__ float g_xe[BB * TU * DD];
__device__ float g_q [BB * TT * DD];
__device__ float g_k [BB * TT * DD];
__device__ float g_v [BB * TT * DD];
__device__ float g_att[BB * TU * TU];     // encoder attention scratch (fp32)
__device__ float g_t1[BB * TT * DD];
__device__ float g_t2[BB * TT * DD];
__device__ float g_tok[BB * TT * DD];
__device__ float g_score[BB * TT];
__device__ int   g_flag[BB * TT];
__device__ int   g_upos[BB * TT];
__device__ int   g_ulist[BB * TU];

// bf16 hi/lo split scratch
__device__ __nv_bfloat16 g_AH[8u*1024*1024];   // A operand
__device__ __nv_bfloat16 g_AL[8u*1024*1024];
__device__ __nv_bfloat16 g_BH[8u*1024*512];    // B operand
__device__ __nv_bfloat16 g_BL[8u*1024*512];
// ALL weights pre-split once: 26 slots of 512x512 (enc qkv+o: 12, dec qkv+o: 12, pw1, pw2)
#define WSLOT (512LL * 512LL)
__device__ __nv_bfloat16 g_WH[26 * 512 * 512];
__device__ __nv_bfloat16 g_WL[26 * 512 * 512];

// ---------------- PE ----------------
__global__ void pe_kernel() {
    int t = blockIdx.x;
    int i = threadIdx.x;                 // 0..255
    float divv = expf((float)(2 * i) * (-9.210340371976184f / (float)DD));
    float ang = (float)t * divv;
    g_pe[t * DD + 2 * i]     = sinf(ang);
    g_pe[t * DD + 2 * i + 1] = cosf(ang);
}

// ---------------- embedding: circular conv1d + PE ----------------
__global__ void embed_kernel(const float* __restrict__ x, const float* __restrict__ cw,
                             float* __restrict__ ex) {
    int t = blockIdx.x, b = blockIdx.y;
    __shared__ float sw[CIN * 3];
    int tid = threadIdx.x;               // 128 threads
    for (int i = tid; i < CIN * 3; i += 128) {
        int c = i / 3, k = i % 3;
        int tt = t + k - 1;
        if (tt < 0) tt += TT;
        if (tt >= TT) tt -= TT;
        sw[i] = x[((long long)b * TT + tt) * CIN + c];
    }
    __syncthreads();
#pragma unroll
    for (int p = 0; p < 4; p++) {
        int d = tid + p * 128;
        const float* w = cw + (long long)d * (CIN * 3);
        float acc = 0.f;
#pragma unroll 15
        for (int i = 0; i < CIN * 3; i++) acc = fmaf(sw[i], w[i], acc);
        ex[((long long)b * TT + t) * DD + d] = acc + g_pe[t * DD + d];
    }
}

// ---------------- windowed mean/var score ----------------
__global__ void score_kernel(const float* __restrict__ ex, float* __restrict__ score) {
    int t = blockIdx.x, b = blockIdx.y;
    int lo = t - (SEQW - 1); if (lo < 0) lo = 0;
    float inv = 1.f / (float)(t + 1 - lo);
    int tid = threadIdx.x;               // 256
    float vs = 0.f, ms = 0.f;
#pragma unroll
    for (int p = 0; p < 2; p++) {
        int d = tid + p * 256;
        float s1 = 0.f, s2 = 0.f;
        for (int w = lo; w <= t; w++) {
            float v = ex[((long long)b * TT + w) * DD + d];
            s1 += v; s2 += v * v;
        }
        float m = s1 * inv, m2 = s2 * inv;
        vs += m2 - m * m;
        ms += m;
    }
    __shared__ float rv[256], rm[256];
    rv[tid] = vs; rm[tid] = ms; __syncthreads();
    for (int s = 128; s > 0; s >>= 1) {
        if (tid < s) { rv[tid] += rv[tid + s]; rm[tid] += rm[tid + s]; }
        __syncthreads();
    }
    if (tid == 0) score[b * TT + t] = rv[0] / rm[0];
}

// ---------------- selection: rank with top_k tie-break ----------------
__global__ void select_kernel() {
    int b = blockIdx.x;
    int t = threadIdx.x;                 // 1024 threads
    __shared__ float ss[TT];
    __shared__ int   sf[TT];
    float myv = g_score[b * TT + t];
    ss[t] = myv;
    __syncthreads();
    int rank = 0;
    for (int i = 0; i < TT; i++) {
        float o = ss[i];
        rank += (o > myv) || (o == myv && i < t);
    }
    int masked = (rank < TRR) ? 1 : 0;
    sf[t] = masked;
    __syncthreads();
    int ucnt = 0;
    for (int i = 0; i < t; i++) ucnt += (sf[i] == 0);
    g_flag[b * TT + t] = masked;
    if (!masked) {
        g_upos[b * TT + t] = ucnt;
        g_ulist[b * TU + ucnt] = t;
    } else {
        g_upos[b * TT + t] = -1;
    }
}

// ---------------- gather unmasked tokens ----------------
__global__ void gather_kernel(const float* __restrict__ ex, float* __restrict__ xe) {
    int p = blockIdx.x, b = blockIdx.y;
    int t = g_ulist[b * TU + p];
    const float* src = ex + ((long long)b * TT + t) * DD;
    float* dst = xe + ((long long)b * TU + p) * DD;
    for (int d = threadIdx.x; d < DD; d += 256) dst[d] = src[d];
}

// ---------------- build decoder tokens ----------------
__global__ void tokens_kernel(const float* __restrict__ ux, const float* __restrict__ mtk,
                              float* __restrict__ tok) {
    int t = blockIdx.x, b = blockIdx.y;
    float* dst = tok + ((long long)b * TT + t) * DD;
    if (g_flag[b * TT + t]) {
        for (int d = threadIdx.x; d < 512; d += 256)
            dst[d] = mtk[d] + g_pe[t * DD + d];
    } else {
        int p = g_upos[b * TT + t];
        const float* src = ux + ((long long)b * TU + p) * DD;
        for (int d = threadIdx.x; d < 512; d += 256) dst[d] = src[d];
    }
}

// ================= split / transpose-split prep kernels =================
__global__ void split_kernel(const float* __restrict__ X, __nv_bfloat16* __restrict__ H,
                             __nv_bfloat16* __restrict__ L, int n4) {
    int i = blockIdx.x * blockDim.x + threadIdx.x;
    if (i >= n4) return;
    float4 v = ((const float4*)X)[i];
    __nv_bfloat16 h0 = __float2bfloat16(v.x), h1 = __float2bfloat16(v.y);
    __nv_bfloat16 h2 = __float2bfloat16(v.z), h3 = __float2bfloat16(v.w);
    float r0 = v.x - __bfloat162float(h0), r1 = v.y - __bfloat162float(h1);
    float r2 = v.z - __bfloat162float(h2), r3 = v.w - __bfloat162float(h3);
    __nv_bfloat162* Hp = (__nv_bfloat162*)H;
    __nv_bfloat162* Lp = (__nv_bfloat162*)L;
    Hp[2*i]   = __halves2bfloat162(h0, h1);
    Hp[2*i+1] = __halves2bfloat162(h2, h3);
    Lp[2*i]   = __floats2bfloat162_rn(r0, r1);
    Lp[2*i+1] = __floats2bfloat162_rn(r2, r3);
}

// X: batch b at X + b*sIn, [R][C] fp32 -> H,L at + b*sOut, [C][R] bf16
__global__ void tsplit_kernel(const float* __restrict__ X, __nv_bfloat16* __restrict__ H,
                              __nv_bfloat16* __restrict__ L, int R, int C,
                              long long sIn, long long sOut) {
    __shared__ float tile[32][33];
    int b = blockIdx.z;
    int c0 = blockIdx.x * 32, r0 = blockIdx.y * 32;
    const float* Xb = X + (long long)b * sIn;
    int tx = threadIdx.x, ty = threadIdx.y;   // 32 x 8
#pragma unroll
    for (int i = ty; i < 32; i += 8)
        tile[i][tx] = Xb[(long long)(r0 + i) * C + c0 + tx];
    __syncthreads();
    long long ob = (long long)b * sOut;
#pragma unroll
    for (int i = ty; i < 32; i += 8) {
        float v = tile[tx][i];                // element (r0+tx, c0+i)
        __nv_bfloat16 h = __float2bfloat16(v);
        float rr = v - __bfloat162float(h);
        long long o = ob + (long long)(c0 + i) * R + r0 + tx;
        H[o] = h;
        L[o] = __float2bfloat16(rr);
    }
}

// ================= tensor-core GEMM on pre-split bf16 =================
// C[b] = epi(alpha * A[b] @ B[b]^T + bias + resid[b])
// A: [M,K] row-major (hi/lo), B: [N,K] n-major (hi/lo). M,N %128==0, K%32==0.
// EXACT R5 structure: 8 warps, warp tile 64x32, 2-stage cp.async.

#define RSTR 40   // halfwords per smem row (32 data + 8 pad) -> 80B rows
#define PARTB (128 * RSTR * 2)     // bytes per part (10240)
#define STAGEB (4 * PARTB)         // bytes per stage (40960)

__device__ __forceinline__ void cpa(u32 dst, const void* src) {
    asm volatile("cp.async.cg.shared.global [%0], [%1], 16;\n" :: "r"(dst), "l"(src));
}
__device__ __forceinline__ void ldsm4(u32* r, u32 addr) {
    asm volatile("ldmatrix.sync.aligned.m8n8.x4.shared.b16 {%0,%1,%2,%3}, [%4];\n"
        : "=r"(r[0]), "=r"(r[1]), "=r"(r[2]), "=r"(r[3]) : "r"(addr));
}
__device__ __forceinline__ void mma16816(float* d, const u32* a, u32 b0, u32 b1) {
    asm volatile(
        "mma.sync.aligned.m16n8k16.row.col.f32.bf16.bf16.f32 "
        "{%0,%1,%2,%3}, {%4,%5,%6,%7}, {%8,%9}, {%0,%1,%2,%3};\n"
        : "+f"(d[0]), "+f"(d[1]), "+f"(d[2]), "+f"(d[3])
        : "r"(a[0]), "r"(a[1]), "r"(a[2]), "r"(a[3]), "r"(b0), "r"(b1));
}

__device__ __forceinline__ void load_stage(
    u32 sbase, const __nv_bfloat16* Ah, const __nv_bfloat16* Al,
    const __nv_bfloat16* Bh, const __nv_bfloat16* Bl,
    int m0, int n0, int K, int k0, int tid) {
    int r = tid >> 2, c = tid & 3;
    u32 off1 = (u32)(r * RSTR + c * 8) * 2;
    u32 off2 = (u32)((r + 64) * RSTR + c * 8) * 2;
    long long a1 = (long long)(m0 + r) * K + k0 + c * 8;
    long long a2 = a1 + (long long)64 * K;
    long long b1 = (long long)(n0 + r) * K + k0 + c * 8;
    long long b2 = b1 + (long long)64 * K;
    cpa(sbase + off1, Ah + a1);               cpa(sbase + off2, Ah + a2);
    cpa(sbase + PARTB + off1, Al + a1);       cpa(sbase + PARTB + off2, Al + a2);
    cpa(sbase + 2*PARTB + off1, Bh + b1);     cpa(sbase + 2*PARTB + off2, Bh + b2);
    cpa(sbase + 3*PARTB + off1, Bl + b1);     cpa(sbase + 3*PARTB + off2, Bl + b2);
    asm volatile("cp.async.commit_group;\n");
}

__global__ __launch_bounds__(256)
void gemm2_kernel(const __nv_bfloat16* __restrict__ Ah, const __nv_bfloat16* __restrict__ Al,
                  const __nv_bfloat16* __restrict__ Bh, const __nv_bfloat16* __restrict__ Bl,
                  const float* __restrict__ bias, const float* __restrict__ resid,
                  float* __restrict__ C, int M, int N, int K,
                  long long sA, long long sB, long long sC,
                  float alpha, int epi) {
    extern __shared__ __nv_bfloat16 smraw[];
    u32 smb = (u32)__cvta_generic_to_shared(smraw);

    int bz = blockIdx.z;
    Ah += (long long)bz * sA; Al += (long long)bz * sA;
    Bh += (long long)bz * sB; Bl += (long long)bz * sB;
    C  += (long long)bz * sC;
    const float* R = resid ? resid + (long long)bz * sC : nullptr;

    int m0 = blockIdx.y * 128, n0 = blockIdx.x * 128;
    int tid = threadIdx.x, lane = tid & 31, wid = tid >> 5;
    int wm = (wid & 1) * 64, wn = (wid >> 1) * 32;
    int g = lane >> 2, t4 = lane & 3;

    float acc[4][4][4];
#pragma unroll
    for (int i = 0; i < 4; i++)
#pragma unroll
        for (int j = 0; j < 4; j++)
#pragma unroll
            for (int q = 0; q < 4; q++) acc[i][j][q] = 0.f;

    int nk = K / 32;
    load_stage(smb, Ah, Al, Bh, Bl, m0, n0, K, 0, tid);
    load_stage(smb + STAGEB, Ah, Al, Bh, Bl, m0, n0, K, 32, tid);

    int arow = lane & 15;
    int achkbase = lane >> 4;                    // +0/+1 k-chunk
    int brow = (lane & 7) + ((lane & 16) >> 1);  // rows 0-7 / 8-15
    int bchkbase = (lane >> 3) & 1;

    for (int kt = 0; kt < nk; kt++) {
        asm volatile("cp.async.wait_group 1;\n");
        __syncthreads();
        u32 base = smb + (kt & 1) * STAGEB;
        u32 aH = base, aL = base + PARTB, bH = base + 2*PARTB, bL = base + 3*PARTB;
#pragma unroll
        for (int kq = 0; kq < 2; kq++) {
            u32 ah[4][4], al[4][4];
            int achk = kq * 2 + achkbase;
#pragma unroll
            for (int mf = 0; mf < 4; mf++) {
                u32 off = (u32)((wm + mf * 16 + arow) * RSTR + achk * 8) * 2;
                ldsm4(ah[mf], aH + off);
                ldsm4(al[mf], aL + off);
            }
            int bchk = kq * 2 + bchkbase;
#pragma unroll
            for (int np = 0; np < 2; np++) {
                u32 off = (u32)((wn + np * 16 + brow) * RSTR + bchk * 8) * 2;
                u32 bh[4], bl[4];
                ldsm4(bh, bH + off);
                ldsm4(bl, bL + off);
#pragma unroll
                for (int ni = 0; ni < 2; ni++) {
                    int nf = np * 2 + ni;
                    u32 b0h = bh[ni*2], b1h = bh[ni*2+1];
                    u32 b0l = bl[ni*2], b1l = bl[ni*2+1];
#pragma unroll
                    for (int mf = 0; mf < 4; mf++) {
                        mma16816(acc[mf][nf], ah[mf], b0h, b1h);
                        mma16816(acc[mf][nf], ah[mf], b0l, b1l);
                        mma16816(acc[mf][nf], al[mf], b0h, b1h);
                    }
                }
            }
        }
        __syncthreads();
        if (kt + 2 < nk)
            load_stage(smb + (kt & 1) * STAGEB, Ah, Al, Bh, Bl, m0, n0, K, (kt + 2) * 32, tid);
        else
            asm volatile("cp.async.commit_group;\n");
    }

    // ---- epilogue ----
#pragma unroll
    for (int mf = 0; mf < 4; mf++) {
        int r0 = m0 + wm + mf * 16 + g;
#pragma unroll
        for (int nf = 0; nf < 4; nf++) {
            int cc = n0 + wn + nf * 8 + t4 * 2;
#pragma unroll
            for (int half = 0; half < 2; half++) {
                int r = r0 + half * 8;
                float v0 = acc[mf][nf][half * 2 + 0] * alpha;
                float v1 = acc[mf][nf][half * 2 + 1] * alpha;
                if (bias) { v0 += bias[cc]; v1 += bias[cc + 1]; }
                if (R) {
                    v0 += R[(long long)r * N + cc];
                    v1 += R[(long long)r * N + cc + 1];
                }
                if (epi == 1) {
                    v0 = 0.5f * v0 * (1.f + erff(v0 * 0.7071067811865475f));
                    v1 = 0.5f * v1 * (1.f + erff(v1 * 0.7071067811865475f));
                } else if (epi == 2) {
                    v0 = 1.f / (1.f + __expf(-v0));
                    v1 = 1.f / (1.f + __expf(-v1));
                }
                *(float2*)(C + (long long)r * N + cc) = make_float2(v0, v1);
            }
        }
    }
}

// ---------------- softmax over rows ----------------
__global__ void softmax_kernel(float* __restrict__ S, int Nc) {
    long long row = blockIdx.x;
    float* p = S + row * Nc;
    __shared__ float red[256];
    int tid = threadIdx.x;
    float mx = -1e30f;
    for (int i = tid; i < Nc; i += 256) mx = fmaxf(mx, p[i]);
    red[tid] = mx; __syncthreads();
    for (int s = 128; s > 0; s >>= 1) { if (tid < s) red[tid] = fmaxf(red[tid], red[tid + s]); __syncthreads(); }
    mx = red[0]; __syncthreads();
    float sum = 0.f;
    for (int i = tid; i < Nc; i += 256) { float e = __expf(p[i] - mx); p[i] = e; sum += e; }
    red[tid] = sum; __syncthreads();
    for (int s = 128; s > 0; s >>= 1) { if (tid < s) red[tid] += red[tid + s]; __syncthreads(); }
    float inv = 1.f / red[0];
    for (int i = tid; i < Nc; i += 256) p[i] *= inv;
}

// ---------------- layer norm (row length 512) ----------------
__global__ void ln_kernel(const float* __restrict__ X, const float* __restrict__ g,
                          const float* __restrict__ b, float* __restrict__ Y) {
    long long row = blockIdx.x;
    const float* x = X + row * DD;
    float* y = Y + row * DD;
    __shared__ float red[256];
    int tid = threadIdx.x;
    float v0 = x[tid], v1 = x[tid + 256];
    red[tid] = v0 + v1; __syncthreads();
    for (int s = 128; s > 0; s >>= 1) { if (tid < s) red[tid] += red[tid + s]; __syncthreads(); }
    float mu = red[0] * (1.f / (float)DD); __syncthreads();
    float d0 = v0 - mu, d1 = v1 - mu;
    red[tid] = d0 * d0 + d1 * d1; __syncthreads();
    for (int s = 128; s > 0; s >>= 1) { if (tid < s) red[tid] += red[tid + s]; __syncthreads(); }
    float inv = rsqrtf(red[0] * (1.f / (float)DD) + 1e-5f);
    y[tid]       = d0 * inv * g[tid] + b[tid];
    y[tid + 256] = d1 * inv * g[tid + 256] + b[tid + 256];
}

// ---------------- host orchestration ----------------
extern "C" void kernel_launch(void* const* d_in, const int* in_sizes, int n_in,
                              void* d_out, int out_size) {
    float *ex, *xe, *q, *k, *v, *att, *t1, *t2, *tok, *score;
    cudaGetSymbolAddress((void**)&ex,  g_ex);
    cudaGetSymbolAddress((void**)&xe,  g_xe);
    cudaGetSymbolAddress((void**)&q,   g_q);
    cudaGetSymbolAddress((void**)&k,   g_k);
    cudaGetSymbolAddress((void**)&v,   g_v);
    cudaGetSymbolAddress((void**)&att, g_att);
    cudaGetSymbolAddress((void**)&t1,  g_t1);
    cudaGetSymbolAddress((void**)&t2,  g_t2);
    cudaGetSymbolAddress((void**)&tok, g_tok);
    cudaGetSymbolAddress((void**)&score, g_score);
    __nv_bfloat16 *AH, *AL, *BH, *BL, *WH, *WL;
    cudaGetSymbolAddress((void**)&AH, g_AH);
    cudaGetSymbolAddress((void**)&AL, g_AL);
    cudaGetSymbolAddress((void**)&BH, g_BH);
    cudaGetSymbolAddress((void**)&BL, g_BL);
    cudaGetSymbolAddress((void**)&WH, g_WH);
    cudaGetSymbolAddress((void**)&WL, g_WL);

    static int smem_set = 0;
    if (!smem_set) {
        cudaFuncSetAttribute(gemm2_kernel, cudaFuncAttributeMaxDynamicSharedMemorySize, 2 * STAGEB);
        smem_set = 1;
    }

    const float* in[31];
    for (int i = 0; i < 31 && i < n_in; i++) in[i] = (const float*)d_in[i];

    const float *x = in[0], *conv_w = in[1], *mask_token = in[2];
    const float *pro_w1, *pro_b1, *pro_w2, *pro_b2;
    const float *eW[4], *eBi[4], *eg, *ebb, *eng, *enb;
    const float *dW[4], *dBi[4], *dg, *dbb, *dng, *dnb;

    bool sig = (in_sizes[3] == LL * DD * DD);
    if (sig) {
        eW[0]=in[3];  eBi[0]=in[4];  eW[1]=in[5];  eBi[1]=in[6];
        eW[2]=in[7];  eBi[2]=in[8];  eW[3]=in[9];  eBi[3]=in[10];
        eg=in[11]; ebb=in[12]; eng=in[13]; enb=in[14];
        dW[0]=in[15]; dBi[0]=in[16]; dW[1]=in[17]; dBi[1]=in[18];
        dW[2]=in[19]; dBi[2]=in[20]; dW[3]=in[21]; dBi[3]=in[22];
        dg=in[23]; dbb=in[24]; dng=in[25]; dnb=in[26];
        pro_w1=in[27]; pro_b1=in[28]; pro_w2=in[29]; pro_b2=in[30];
    } else {
        pro_w1=in[3]; pro_b1=in[4]; pro_w2=in[5]; pro_b2=in[6];
        eW[0]=in[7];  eW[1]=in[8];  eW[2]=in[9];  eW[3]=in[10];
        eBi[0]=in[11]; eBi[1]=in[12]; eBi[2]=in[13]; eBi[3]=in[14];
        eg=in[15]; ebb=in[16]; eng=in[17]; enb=in[18];
        dW[0]=in[19]; dW[1]=in[20]; dW[2]=in[21]; dW[3]=in[22];
        dBi[0]=in[23]; dBi[1]=in[24]; dBi[2]=in[25]; dBi[3]=in[26];
        dg=in[27]; dbb=in[28]; dng=in[29]; dnb=in[30];
    }

    const float SCALE = 0.044194173824159216f;  // 1/sqrt(512)

    // weight slot offsets (each WSLOT elements): enc q,k,v,o = 0..3 (x LL), dec = 12..23, pw1=24, pw2=25
    auto wslot = [&](int s) { return (long long)s * WSLOT; };

    auto split = [&](const float* X, __nv_bfloat16* H, __nv_bfloat16* L, long long n) {
        int n4 = (int)(n / 4);
        split_kernel<<<(n4 + 255) / 256, 256>>>(X, H, L, n4);
    };
    auto tsplitS = [&](const float* X, __nv_bfloat16* H, __nv_bfloat16* L,
                       int R, int C, long long sIn, long long sOut, int nb) {
        tsplit_kernel<<<dim3(C / 32, R / 32, nb), dim3(32, 8)>>>(X, H, L, R, C, sIn, sOut);
    };
    auto gemm = [&](const __nv_bfloat16* ah, const __nv_bfloat16* al,
                    const __nv_bfloat16* bh, const __nv_bfloat16* bl,
                    const float* bias, const float* resid, float* C,
                    int M, int N, int K, long long sA, long long sB, long long sC,
                    int nb, float alpha, int epi) {
        dim3 grid(N / 128, M / 128, nb);
        gemm2_kernel<<<grid, 256, 2 * STAGEB>>>(ah, al, bh, bl, bias, resid, C,
                                                M, N, K, sA, sB, sC, alpha, epi);
    };

    // ---- pre-split ALL weights once, batched over layers (off the critical path) ----
    // enc q/k/v/o at slots 0,3,6,9 (+layer), i.e. slot base s*3? Use: enc W[i] layer l -> slot i*3 + l
    for (int i = 0; i < 4; i++)
        tsplitS(eW[i], WH + wslot(i * 3), WL + wslot(i * 3), DD, DD, WSLOT, WSLOT, LL);
    for (int i = 0; i < 4; i++)
        tsplitS(dW[i], WH + wslot(12 + i * 3), WL + wslot(12 + i * 3), DD, DD, WSLOT, WSLOT, LL);
    tsplitS(pro_w1, WH + wslot(24), WL + wslot(24), DD, DD, WSLOT, WSLOT, 1);
    tsplitS(pro_w2, WH + wslot(25), WL + wslot(25), DD, DD, WSLOT, WSLOT, 1);

    // ---- embedding + score + selection ----
    pe_kernel<<<TT, 256>>>();
    embed_kernel<<<dim3(TT, BB), 128>>>(x, conv_w, ex);
    score_kernel<<<dim3(TT, BB), 256>>>(ex, score);
    select_kernel<<<BB, TT>>>();
    gather_kernel<<<dim3(TU, BB), 256>>>(ex, xe);

    // ---- encoder (Tc = 512) ----
    {
        int Tc = TU, BT = BB * Tc;
        long long sQK = (long long)Tc * DD, sAtt = (long long)Tc * Tc;
        for (int l = 0; l < LL; l++) {
            const float *bq = eBi[0] + l * DD, *bk = eBi[1] + l * DD;
            const float *bv = eBi[2] + l * DD, *bo = eBi[3] + l * DD;
            const __nv_bfloat16 *WqH = WH + wslot(0 * 3 + l), *WqL = WL + wslot(0 * 3 + l);
            const __nv_bfloat16 *WkH = WH + wslot(1 * 3 + l), *WkL = WL + wslot(1 * 3 + l);
            const __nv_bfloat16 *WvH = WH + wslot(2 * 3 + l), *WvL = WL + wslot(2 * 3 + l);
            const __nv_bfloat16 *WoH = WH + wslot(3 * 3 + l), *WoL = WL + wslot(3 * 3 + l);
            split(xe, AH, AL, (long long)BT * DD);
            gemm(AH, AL, WqH, WqL, bq, nullptr, q, BT, DD, DD, 0, 0, 0, 1, 1.f, 0);
            gemm(AH, AL, WkH, WkL, bk, nullptr, k, BT, DD, DD, 0, 0, 0, 1, 1.f, 0);
            gemm(AH, AL, WvH, WvL, bv, nullptr, v, BT, DD, DD, 0, 0, 0, 1, 1.f, 0);
            split(q, AH, AL, (long long)BT * DD);
            split(k, BH, BL, (long long)BT * DD);
            gemm(AH, AL, BH, BL, nullptr, nullptr, att, Tc, Tc, DD, sQK, sQK, sAtt, BB, SCALE, 0);
            softmax_kernel<<<BB * Tc, 256>>>(att, Tc);
            split(att, AH, AL, (long long)BB * Tc * Tc);
            tsplitS(v, BH, BL, Tc, DD, sQK, sQK, BB);     // [b][D][Tc]
            gemm(AH, AL, BH, BL, nullptr, xe, t1, Tc, DD, Tc, sAtt, sQK, sQK, BB, 1.f, 0);
            ln_kernel<<<BT, 256>>>(t1, eg + l * DD, ebb + l * DD, t2);
            split(t2, AH, AL, (long long)BT * DD);
            gemm(AH, AL, WoH, WoL, bo, t1, xe, BT, DD, DD, 0, 0, 0, 1, 1.f, 0);
        }
        ln_kernel<<<BT, 256>>>(xe, eng, enb, t1);    // ux in t1
    }

    // ---- decoder tokens ----
    tokens_kernel<<<dim3(TT, BB), 256>>>(t1, mask_token, tok);

    // ---- decoder (Tc = 1024), attention maps into d_out ----
    {
        int Tc = TT, BT = BB * Tc;
        long long sQK = (long long)Tc * DD, sAtt = (long long)Tc * Tc;
        for (int l = 0; l < LL; l++) {
            const float *bq = dBi[0] + l * DD, *bk = dBi[1] + l * DD;
            const float *bv = dBi[2] + l * DD, *bo = dBi[3] + l * DD;
            const __nv_bfloat16 *WqH = WH + wslot(12 + 0 * 3 + l), *WqL = WL + wslot(12 + 0 * 3 + l);
            const __nv_bfloat16 *WkH = WH + wslot(12 + 1 * 3 + l), *WkL = WL + wslot(12 + 1 * 3 + l);
            const __nv_bfloat16 *WvH = WH + wslot(12 + 2 * 3 + l), *WvL = WL + wslot(12 + 2 * 3 + l);
            const __nv_bfloat16 *WoH = WH + wslot(12 + 3 * 3 + l), *WoL = WL + wslot(12 + 3 * 3 + l);
            float* attOut = (float*)d_out + (long long)l * BB * TT * TT;
            split(tok, AH, AL, (long long)BT * DD);
            gemm(AH, AL, WqH, WqL, bq, nullptr, q, BT, DD, DD, 0, 0, 0, 1, 1.f, 0);
            gemm(AH, AL, WkH, WkL, bk, nullptr, k, BT, DD, DD, 0, 0, 0, 1, 1.f, 0);
            gemm(AH, AL, WvH, WvL, bv, nullptr, v, BT, DD, DD, 0, 0, 0, 1, 1.f, 0);
            split(q, AH, AL, (long long)BT * DD);
            split(k, BH, BL, (long long)BT * DD);
            gemm(AH, AL, BH, BL, nullptr, nullptr, attOut, Tc, Tc, DD, sQK, sQK, sAtt, BB, SCALE, 0);
            softmax_kernel<<<BB * Tc, 256>>>(attOut, Tc);
            split(attOut, AH, AL, (long long)BB * Tc * Tc);
            tsplitS(v, BH, BL, Tc, DD, sQK, sQK, BB);     // [b][D][Tc]
            gemm(AH, AL, BH, BL, nullptr, tok, t1, Tc, DD, Tc, sAtt, sQK, sQK, BB, 1.f, 0);
            ln_kernel<<<BT, 256>>>(t1, dg + l * DD, dbb + l * DD, t2);
            split(t2, AH, AL, (long long)BT * DD);
            gemm(AH, AL, WoH, WoL, bo, t1, tok, BT, DD, DD, 0, 0, 0, 1, 1.f, 0);
        }
        ln_kernel<<<BB * TT, 256>>>(tok, dng, dnb, t1);   // dx in t1

        // ---- projector: rec = sigmoid(gelu(dx@W1+b1)@W2+b2) ----
        float* rec = (float*)d_out + (long long)LL * BB * TT * TT;
        split(t1, AH, AL, (long long)BB * TT * DD);
        gemm(AH, AL, WH + wslot(24), WL + wslot(24), pro_b1, nullptr, t2,
             BB * TT, DD, DD, 0, 0, 0, 1, 1.f, 1);
        split(t2, AH, AL, (long long)BB * TT * DD);
        gemm(AH, AL, WH + wslot(25), WL + wslot(25), pro_b2, nullptr, rec,
             BB * TT, DD, DD, 0, 0, 0, 1, 1.f, 2);
    }
}

// round 16
// speedup vs baseline: 1.6885x; 1.0254x over previous
#include <cuda_runtime.h>
#include <cuda_bf16.h>
#include <stdint.h>
#include <math.h>

typedef unsigned int u32;

// ---------------- problem constants ----------------
#define BB 8
#define TT 1024
#define CIN 55
#define DD 512
#define LL 3
#define SEQW 10
#define TRR 512          // masked count
#define TU 512           // unmasked count (T - TR)

// ---------------- device scratch ----------------
__device__ float g_pe[TT * DD];
__device__ float g_ex[BB * TT * DD];
__device__ float g_xe[BB * TU * DD];
__device__ float g_qkv[3u * BB * TT * DD];   // q | k | v regions
__device__ float g_att[BB * TU * TU];
__device__ float g_t1[BB * TT * DD];
__device__ float g_t2[BB * TT * DD];
__device__ float g_tok[BB * TT * DD];
__device__ float g_score[BB * TT];
__device__ int   g_flag[BB * TT];
__device__ int   g_upos[BB * TT];
__device__ int   g_ulist[BB * TU];

// bf16 hi/lo split scratch
__device__ __nv_bfloat16 g_AH[8u*1024*1024];   // A operand (also q+k HL)
__device__ __nv_bfloat16 g_AL[8u*1024*1024];
__device__ __nv_bfloat16 g_BH[8u*1024*512];    // B operand
__device__ __nv_bfloat16 g_BL[8u*1024*512];
// ALL weights pre-split once: 26 slots of 512x512
#define WSLOT (512LL * 512LL)
__device__ __nv_bfloat16 g_WH[26 * 512 * 512];
__device__ __nv_bfloat16 g_WL[26 * 512 * 512];

// ---------------- PE ----------------
__global__ void pe_kernel() {
    int t = blockIdx.x;
    int i = threadIdx.x;                 // 0..255
    float divv = expf((float)(2 * i) * (-9.210340371976184f / (float)DD));
    float ang = (float)t * divv;
    g_pe[t * DD + 2 * i]     = sinf(ang);
    g_pe[t * DD + 2 * i + 1] = cosf(ang);
}

// ---------------- embedding: circular conv1d + PE ----------------
__global__ void embed_kernel(const float* __restrict__ x, const float* __restrict__ cw,
                             float* __restrict__ ex) {
    int t = blockIdx.x, b = blockIdx.y;
    __shared__ float sw[CIN * 3];
    int tid = threadIdx.x;               // 128 threads
    for (int i = tid; i < CIN * 3; i += 128) {
        int c = i / 3, k = i % 3;
        int tt = t + k - 1;
        if (tt < 0) tt += TT;
        if (tt >= TT) tt -= TT;
        sw[i] = x[((long long)b * TT + tt) * CIN + c];
    }
    __syncthreads();
#pragma unroll
    for (int p = 0; p < 4; p++) {
        int d = tid + p * 128;
        const float* w = cw + (long long)d * (CIN * 3);
        float acc = 0.f;
#pragma unroll 15
        for (int i = 0; i < CIN * 3; i++) acc = fmaf(sw[i], w[i], acc);
        ex[((long long)b * TT + t) * DD + d] = acc + g_pe[t * DD + d];
    }
}

// ---------------- windowed mean/var score ----------------
__global__ void score_kernel(const float* __restrict__ ex, float* __restrict__ score) {
    int t = blockIdx.x, b = blockIdx.y;
    int lo = t - (SEQW - 1); if (lo < 0) lo = 0;
    float inv = 1.f / (float)(t + 1 - lo);
    int tid = threadIdx.x;               // 256
    float vs = 0.f, ms = 0.f;
#pragma unroll
    for (int p = 0; p < 2; p++) {
        int d = tid + p * 256;
        float s1 = 0.f, s2 = 0.f;
        for (int w = lo; w <= t; w++) {
            float v = ex[((long long)b * TT + w) * DD + d];
            s1 += v; s2 += v * v;
        }
        float m = s1 * inv, m2 = s2 * inv;
        vs += m2 - m * m;
        ms += m;
    }
    __shared__ float rv[256], rm[256];
    rv[tid] = vs; rm[tid] = ms; __syncthreads();
    for (int s = 128; s > 0; s >>= 1) {
        if (tid < s) { rv[tid] += rv[tid + s]; rm[tid] += rm[tid + s]; }
        __syncthreads();
    }
    if (tid == 0) score[b * TT + t] = rv[0] / rm[0];
}

// ---------------- selection: rank with top_k tie-break ----------------
__global__ void select_kernel() {
    int b = blockIdx.x;
    int t = threadIdx.x;                 // 1024 threads
    __shared__ float ss[TT];
    __shared__ int   sf[TT];
    float myv = g_score[b * TT + t];
    ss[t] = myv;
    __syncthreads();
    int rank = 0;
    for (int i = 0; i < TT; i++) {
        float o = ss[i];
        rank += (o > myv) || (o == myv && i < t);
    }
    int masked = (rank < TRR) ? 1 : 0;
    sf[t] = masked;
    __syncthreads();
    int ucnt = 0;
    for (int i = 0; i < t; i++) ucnt += (sf[i] == 0);
    g_flag[b * TT + t] = masked;
    if (!masked) {
        g_upos[b * TT + t] = ucnt;
        g_ulist[b * TU + ucnt] = t;
    } else {
        g_upos[b * TT + t] = -1;
    }
}

// ---------------- gather unmasked tokens ----------------
__global__ void gather_kernel(const float* __restrict__ ex, float* __restrict__ xe) {
    int p = blockIdx.x, b = blockIdx.y;
    int t = g_ulist[b * TU + p];
    const float* src = ex + ((long long)b * TT + t) * DD;
    float* dst = xe + ((long long)b * TU + p) * DD;
    for (int d = threadIdx.x; d < DD; d += 256) dst[d] = src[d];
}

// ---------------- build decoder tokens ----------------
__global__ void tokens_kernel(const float* __restrict__ ux, const float* __restrict__ mtk,
                              float* __restrict__ tok) {
    int t = blockIdx.x, b = blockIdx.y;
    float* dst = tok + ((long long)b * TT + t) * DD;
    if (g_flag[b * TT + t]) {
        for (int d = threadIdx.x; d < 512; d += 256)
            dst[d] = mtk[d] + g_pe[t * DD + d];
    } else {
        int p = g_upos[b * TT + t];
        const float* src = ux + ((long long)b * TU + p) * DD;
        for (int d = threadIdx.x; d < 512; d += 256) dst[d] = src[d];
    }
}

// ================= split / transpose-split prep kernels =================
__global__ void split_kernel(const float* __restrict__ X, __nv_bfloat16* __restrict__ H,
                             __nv_bfloat16* __restrict__ L, int n4) {
    int i = blockIdx.x * blockDim.x + threadIdx.x;
    if (i >= n4) return;
    float4 v = ((const float4*)X)[i];
    __nv_bfloat16 h0 = __float2bfloat16(v.x), h1 = __float2bfloat16(v.y);
    __nv_bfloat16 h2 = __float2bfloat16(v.z), h3 = __float2bfloat16(v.w);
    float r0 = v.x - __bfloat162float(h0), r1 = v.y - __bfloat162float(h1);
    float r2 = v.z - __bfloat162float(h2), r3 = v.w - __bfloat162float(h3);
    __nv_bfloat162* Hp = (__nv_bfloat162*)H;
    __nv_bfloat162* Lp = (__nv_bfloat162*)L;
    Hp[2*i]   = __halves2bfloat162(h0, h1);
    Hp[2*i+1] = __halves2bfloat162(h2, h3);
    Lp[2*i]   = __floats2bfloat162_rn(r0, r1);
    Lp[2*i+1] = __floats2bfloat162_rn(r2, r3);
}

// X: batch b at X + b*sIn, [R][C] fp32 -> H,L at + b*sOut, [C][R] bf16
__global__ void tsplit_kernel(const float* __restrict__ X, __nv_bfloat16* __restrict__ H,
                              __nv_bfloat16* __restrict__ L, int R, int C,
                              long long sIn, long long sOut) {
    __shared__ float tile[32][33];
    int b = blockIdx.z;
    int c0 = blockIdx.x * 32, r0 = blockIdx.y * 32;
    const float* Xb = X + (long long)b * sIn;
    int tx = threadIdx.x, ty = threadIdx.y;   // 32 x 8
#pragma unroll
    for (int i = ty; i < 32; i += 8)
        tile[i][tx] = Xb[(long long)(r0 + i) * C + c0 + tx];
    __syncthreads();
    long long ob = (long long)b * sOut;
#pragma unroll
    for (int i = ty; i < 32; i += 8) {
        float v = tile[tx][i];                // element (r0+tx, c0+i)
        __nv_bfloat16 h = __float2bfloat16(v);
        float rr = v - __bfloat162float(h);
        long long o = ob + (long long)(c0 + i) * R + r0 + tx;
        H[o] = h;
        L[o] = __float2bfloat16(rr);
    }
}

// ================= tensor-core GEMM on pre-split bf16 =================
// EXACT R5 loop: 8 warps, warp tile 64x32, 2-stage cp.async.

#define RSTR 40   // halfwords per smem row (32 data + 8 pad) -> 80B rows
#define PARTB (128 * RSTR * 2)     // bytes per part (10240)
#define STAGEB (4 * PARTB)         // bytes per stage (40960)

__device__ __forceinline__ void cpa(u32 dst, const void* src) {
    asm volatile("cp.async.cg.shared.global [%0], [%1], 16;\n" :: "r"(dst), "l"(src));
}
__device__ __forceinline__ void ldsm4(u32* r, u32 addr) {
    asm volatile("ldmatrix.sync.aligned.m8n8.x4.shared.b16 {%0,%1,%2,%3}, [%4];\n"
        : "=r"(r[0]), "=r"(r[1]), "=r"(r[2]), "=r"(r[3]) : "r"(addr));
}
__device__ __forceinline__ void mma16816(float* d, const u32* a, u32 b0, u32 b1) {
    asm volatile(
        "mma.sync.aligned.m16n8k16.row.col.f32.bf16.bf16.f32 "
        "{%0,%1,%2,%3}, {%4,%5,%6,%7}, {%8,%9}, {%0,%1,%2,%3};\n"
        : "+f"(d[0]), "+f"(d[1]), "+f"(d[2]), "+f"(d[3])
        : "r"(a[0]), "r"(a[1]), "r"(a[2]), "r"(a[3]), "r"(b0), "r"(b1));
}

__device__ __forceinline__ void load_stage(
    u32 sbase, const __nv_bfloat16* Ah, const __nv_bfloat16* Al,
    const __nv_bfloat16* Bh, const __nv_bfloat16* Bl,
    int m0, int n0, int K, int k0, int tid) {
    int r = tid >> 2, c = tid & 3;
    u32 off1 = (u32)(r * RSTR + c * 8) * 2;
    u32 off2 = (u32)((r + 64) * RSTR + c * 8) * 2;
    long long a1 = (long long)(m0 + r) * K + k0 + c * 8;
    long long a2 = a1 + (long long)64 * K;
    long long b1 = (long long)(n0 + r) * K + k0 + c * 8;
    long long b2 = b1 + (long long)64 * K;
    cpa(sbase + off1, Ah + a1);               cpa(sbase + off2, Ah + a2);
    cpa(sbase + PARTB + off1, Al + a1);       cpa(sbase + PARTB + off2, Al + a2);
    cpa(sbase + 2*PARTB + off1, Bh + b1);     cpa(sbase + 2*PARTB + off2, Bh + b2);
    cpa(sbase + 3*PARTB + off1, Bl + b1);     cpa(sbase + 3*PARTB + off2, Bl + b2);
    asm volatile("cp.async.commit_group;\n");
}

// core compute loop shared textually by both kernels (macro to keep regalloc per-kernel)
#define GEMM_CORE(ACC)                                                                 \
    int nk = K / 32;                                                                   \
    load_stage(smb, Ah, Al, Bh, Bl, m0, n0, K, 0, tid);                                \
    load_stage(smb + STAGEB, Ah, Al, Bh, Bl, m0, n0, K, 32, tid);                      \
    int arow = lane & 15;                                                              \
    int achkbase = lane >> 4;                                                          \
    int brow = (lane & 7) + ((lane & 16) >> 1);                                        \
    int bchkbase = (lane >> 3) & 1;                                                    \
    for (int kt = 0; kt < nk; kt++) {                                                  \
        asm volatile("cp.async.wait_group 1;\n");                                      \
        __syncthreads();                                                               \
        u32 base = smb + (kt & 1) * STAGEB;                                            \
        u32 aH = base, aL = base + PARTB, bH = base + 2*PARTB, bL = base + 3*PARTB;    \
        _Pragma("unroll")                                                              \
        for (int kq = 0; kq < 2; kq++) {                                               \
            u32 ah[4][4], al[4][4];                                                    \
            int achk = kq * 2 + achkbase;                                              \
            _Pragma("unroll")                                                          \
            for (int mf = 0; mf < 4; mf++) {                                           \
                u32 off = (u32)((wm + mf * 16 + arow) * RSTR + achk * 8) * 2;          \
                ldsm4(ah[mf], aH + off);                                               \
                ldsm4(al[mf], aL + off);                                               \
            }                                                                          \
            int bchk = kq * 2 + bchkbase;                                              \
            _Pragma("unroll")                                                          \
            for (int np = 0; np < 2; np++) {                                           \
                u32 off = (u32)((wn + np * 16 + brow) * RSTR + bchk * 8) * 2;          \
                u32 bh[4], bl[4];                                                      \
                ldsm4(bh, bH + off);                                                   \
                ldsm4(bl, bL + off);                                                   \
                _Pragma("unroll")                                                      \
                for (int ni = 0; ni < 2; ni++) {                                       \
                    int nf = np * 2 + ni;                                              \
                    u32 b0h = bh[ni*2], b1h = bh[ni*2+1];                              \
                    u32 b0l = bl[ni*2], b1l = bl[ni*2+1];                              \
                    _Pragma("unroll")                                                  \
                    for (int mf = 0; mf < 4; mf++) {                                   \
                        mma16816(ACC[mf][nf], ah[mf], b0h, b1h);                       \
                        mma16816(ACC[mf][nf], ah[mf], b0l, b1l);                       \
                        mma16816(ACC[mf][nf], al[mf], b0h, b1h);                       \
                    }                                                                  \
                }                                                                      \
            }                                                                          \
        }                                                                              \
        __syncthreads();                                                               \
        if (kt + 2 < nk)                                                               \
            load_stage(smb + (kt & 1) * STAGEB, Ah, Al, Bh, Bl, m0, n0, K,             \
                       (kt + 2) * 32, tid);                                            \
        else                                                                           \
            asm volatile("cp.async.commit_group;\n");                                  \
    }

__global__ __launch_bounds__(256)
void gemm2_kernel(const __nv_bfloat16* __restrict__ Ah, const __nv_bfloat16* __restrict__ Al,
                  const __nv_bfloat16* __restrict__ Bh, const __nv_bfloat16* __restrict__ Bl,
                  const float* __restrict__ bias, const float* __restrict__ resid,
                  float* __restrict__ C, int M, int N, int K,
                  long long sA, long long sB, long long sC,
                  float alpha, int epi) {
    extern __shared__ __nv_bfloat16 smraw[];
    u32 smb = (u32)__cvta_generic_to_shared(smraw);

    int bz = blockIdx.z;
    Ah += (long long)bz * sA; Al += (long long)bz * sA;
    Bh += (long long)bz * sB; Bl += (long long)bz * sB;
    C  += (long long)bz * sC;
    const float* R = resid ? resid + (long long)bz * sC : nullptr;

    int m0 = blockIdx.y * 128, n0 = blockIdx.x * 128;
    int tid = threadIdx.x, lane = tid & 31, wid = tid >> 5;
    int wm = (wid & 1) * 64, wn = (wid >> 1) * 32;
    int g = lane >> 2, t4 = lane & 3;

    float acc[4][4][4];
#pragma unroll
    for (int i = 0; i < 4; i++)
#pragma unroll
        for (int j = 0; j < 4; j++)
#pragma unroll
            for (int q = 0; q < 4; q++) acc[i][j][q] = 0.f;

    GEMM_CORE(acc)

    // ---- epilogue ----
#pragma unroll
    for (int mf = 0; mf < 4; mf++) {
        int r0 = m0 + wm + mf * 16 + g;
#pragma unroll
        for (int nf = 0; nf < 4; nf++) {
            int cc = n0 + wn + nf * 8 + t4 * 2;
#pragma unroll
            for (int half = 0; half < 2; half++) {
                int r = r0 + half * 8;
                float v0 = acc[mf][nf][half * 2 + 0] * alpha;
                float v1 = acc[mf][nf][half * 2 + 1] * alpha;
                if (bias) { v0 += bias[cc]; v1 += bias[cc + 1]; }
                if (R) {
                    v0 += R[(long long)r * N + cc];
                    v1 += R[(long long)r * N + cc + 1];
                }
                if (epi == 1) {
                    v0 = 0.5f * v0 * (1.f + erff(v0 * 0.7071067811865475f));
                    v1 = 0.5f * v1 * (1.f + erff(v1 * 0.7071067811865475f));
                } else if (epi == 2) {
                    v0 = 1.f / (1.f + __expf(-v0));
                    v1 = 1.f / (1.f + __expf(-v1));
                }
                *(float2*)(C + (long long)r * N + cc) = make_float2(v0, v1);
            }
        }
    }
}

// ---- batched QKV projection: grid.z selects q/k/v (weight stride sB, bias select) ----
__global__ __launch_bounds__(256)
void gemm_qkv_kernel(const __nv_bfloat16* __restrict__ Ah, const __nv_bfloat16* __restrict__ Al,
                     const __nv_bfloat16* __restrict__ Bh, const __nv_bfloat16* __restrict__ Bl,
                     const float* __restrict__ b0p, const float* __restrict__ b1p,
                     const float* __restrict__ b2p,
                     float* __restrict__ C, int M, int N, int K,
                     long long sB, long long sC) {
    extern __shared__ __nv_bfloat16 smraw[];
    u32 smb = (u32)__cvta_generic_to_shared(smraw);

    int bz = blockIdx.z;
    Bh += (long long)bz * sB; Bl += (long long)bz * sB;
    C  += (long long)bz * sC;
    const float* bias = (bz == 0) ? b0p : (bz == 1) ? b1p : b2p;

    int m0 = blockIdx.y * 128, n0 = blockIdx.x * 128;
    int tid = threadIdx.x, lane = tid & 31, wid = tid >> 5;
    int wm = (wid & 1) * 64, wn = (wid >> 1) * 32;
    int g = lane >> 2, t4 = lane & 3;

    float acc[4][4][4];
#pragma unroll
    for (int i = 0; i < 4; i++)
#pragma unroll
        for (int j = 0; j < 4; j++)
#pragma unroll
            for (int q = 0; q < 4; q++) acc[i][j][q] = 0.f;

    GEMM_CORE(acc)

#pragma unroll
    for (int mf = 0; mf < 4; mf++) {
        int r0 = m0 + wm + mf * 16 + g;
#pragma unroll
        for (int nf = 0; nf < 4; nf++) {
            int cc = n0 + wn + nf * 8 + t4 * 2;
#pragma unroll
            for (int half = 0; half < 2; half++) {
                int r = r0 + half * 8;
                float v0 = acc[mf][nf][half * 2 + 0] + bias[cc];
                float v1 = acc[mf][nf][half * 2 + 1] + bias[cc + 1];
                *(float2*)(C + (long long)r * N + cc) = make_float2(v0, v1);
            }
        }
    }
}

// ---------------- softmax over rows ----------------
__global__ void softmax_kernel(float* __restrict__ S, int Nc) {
    long long row = blockIdx.x;
    float* p = S + row * Nc;
    __shared__ float red[256];
    int tid = threadIdx.x;
    float mx = -1e30f;
    for (int i = tid; i < Nc; i += 256) mx = fmaxf(mx, p[i]);
    red[tid] = mx; __syncthreads();
    for (int s = 128; s > 0; s >>= 1) { if (tid < s) red[tid] = fmaxf(red[tid], red[tid + s]); __syncthreads(); }
    mx = red[0]; __syncthreads();
    float sum = 0.f;
    for (int i = tid; i < Nc; i += 256) { float e = __expf(p[i] - mx); p[i] = e; sum += e; }
    red[tid] = sum; __syncthreads();
    for (int s = 128; s > 0; s >>= 1) { if (tid < s) red[tid] += red[tid + s]; __syncthreads(); }
    float inv = 1.f / red[0];
    for (int i = tid; i < Nc; i += 256) p[i] *= inv;
}

// ---------------- layer norm (row length 512) ----------------
__global__ void ln_kernel(const float* __restrict__ X, const float* __restrict__ g,
                          const float* __restrict__ b, float* __restrict__ Y) {
    long long row = blockIdx.x;
    const float* x = X + row * DD;
    float* y = Y + row * DD;
    __shared__ float red[256];
    int tid = threadIdx.x;
    float v0 = x[tid], v1 = x[tid + 256];
    red[tid] = v0 + v1; __syncthreads();
    for (int s = 128; s > 0; s >>= 1) { if (tid < s) red[tid] += red[tid + s]; __syncthreads(); }
    float mu = red[0] * (1.f / (float)DD); __syncthreads();
    float d0 = v0 - mu, d1 = v1 - mu;
    red[tid] = d0 * d0 + d1 * d1; __syncthreads();
    for (int s = 128; s > 0; s >>= 1) { if (tid < s) red[tid] += red[tid + s]; __syncthreads(); }
    float inv = rsqrtf(red[0] * (1.f / (float)DD) + 1e-5f);
    y[tid]       = d0 * inv * g[tid] + b[tid];
    y[tid + 256] = d1 * inv * g[tid + 256] + b[tid + 256];
}

// ---------------- host orchestration ----------------
extern "C" void kernel_launch(void* const* d_in, const int* in_sizes, int n_in,
                              void* d_out, int out_size) {
    float *ex, *xe, *qkv, *att, *t1, *t2, *tok, *score;
    cudaGetSymbolAddress((void**)&ex,  g_ex);
    cudaGetSymbolAddress((void**)&xe,  g_xe);
    cudaGetSymbolAddress((void**)&qkv, g_qkv);
    cudaGetSymbolAddress((void**)&att, g_att);
    cudaGetSymbolAddress((void**)&t1,  g_t1);
    cudaGetSymbolAddress((void**)&t2,  g_t2);
    cudaGetSymbolAddress((void**)&tok, g_tok);
    cudaGetSymbolAddress((void**)&score, g_score);
    __nv_bfloat16 *AH, *AL, *BH, *BL, *WH, *WL;
    cudaGetSymbolAddress((void**)&AH, g_AH);
    cudaGetSymbolAddress((void**)&AL, g_AL);
    cudaGetSymbolAddress((void**)&BH, g_BH);
    cudaGetSymbolAddress((void**)&BL, g_BL);
    cudaGetSymbolAddress((void**)&WH, g_WH);
    cudaGetSymbolAddress((void**)&WL, g_WL);

    static int smem_set = 0;
    if (!smem_set) {
        cudaFuncSetAttribute(gemm2_kernel, cudaFuncAttributeMaxDynamicSharedMemorySize, 2 * STAGEB);
        cudaFuncSetAttribute(gemm_qkv_kernel, cudaFuncAttributeMaxDynamicSharedMemorySize, 2 * STAGEB);
        smem_set = 1;
    }

    const float* in[31];
    for (int i = 0; i < 31 && i < n_in; i++) in[i] = (const float*)d_in[i];

    const float *x = in[0], *conv_w = in[1], *mask_token = in[2];
    const float *pro_w1, *pro_b1, *pro_w2, *pro_b2;
    const float *eW[4], *eBi[4], *eg, *ebb, *eng, *enb;
    const float *dW[4], *dBi[4], *dg, *dbb, *dng, *dnb;

    bool sig = (in_sizes[3] == LL * DD * DD);
    if (sig) {
        eW[0]=in[3];  eBi[0]=in[4];  eW[1]=in[5];  eBi[1]=in[6];
        eW[2]=in[7];  eBi[2]=in[8];  eW[3]=in[9];  eBi[3]=in[10];
        eg=in[11]; ebb=in[12]; eng=in[13]; enb=in[14];
        dW[0]=in[15]; dBi[0]=in[16]; dW[1]=in[17]; dBi[1]=in[18];
        dW[2]=in[19]; dBi[2]=in[20]; dW[3]=in[21]; dBi[3]=in[22];
        dg=in[23]; dbb=in[24]; dng=in[25]; dnb=in[26];
        pro_w1=in[27]; pro_b1=in[28]; pro_w2=in[29]; pro_b2=in[30];
    } else {
        pro_w1=in[3]; pro_b1=in[4]; pro_w2=in[5]; pro_b2=in[6];
        eW[0]=in[7];  eW[1]=in[8];  eW[2]=in[9];  eW[3]=in[10];
        eBi[0]=in[11]; eBi[1]=in[12]; eBi[2]=in[13]; eBi[3]=in[14];
        eg=in[15]; ebb=in[16]; eng=in[17]; enb=in[18];
        dW[0]=in[19]; dW[1]=in[20]; dW[2]=in[21]; dW[3]=in[22];
        dBi[0]=in[23]; dBi[1]=in[24]; dBi[2]=in[25]; dBi[3]=in[26];
        dg=in[27]; dbb=in[28]; dng=in[29]; dnb=in[30];
    }

    const float SCALE = 0.044194173824159216f;  // 1/sqrt(512)

    // weight slots: enc W[i] layer l -> slot i*3+l (i=0 q, 1 k, 2 v, 3 o); dec at +12; pw1=24, pw2=25
    auto wslot = [&](int s) { return (long long)s * WSLOT; };

    auto split = [&](const float* X, __nv_bfloat16* H, __nv_bfloat16* L, long long n) {
        int n4 = (int)(n / 4);
        split_kernel<<<(n4 + 255) / 256, 256>>>(X, H, L, n4);
    };
    auto tsplitS = [&](const float* X, __nv_bfloat16* H, __nv_bfloat16* L,
                       int R, int C, long long sIn, long long sOut, int nb) {
        tsplit_kernel<<<dim3(C / 32, R / 32, nb), dim3(32, 8)>>>(X, H, L, R, C, sIn, sOut);
    };
    auto gemm = [&](const __nv_bfloat16* ah, const __nv_bfloat16* al,
                    const __nv_bfloat16* bh, const __nv_bfloat16* bl,
                    const float* bias, const float* resid, float* C,
                    int M, int N, int K, long long sA, long long sB, long long sC,
                    int nb, float alpha, int epi) {
        dim3 grid(N / 128, M / 128, nb);
        gemm2_kernel<<<grid, 256, 2 * STAGEB>>>(ah, al, bh, bl, bias, resid, C,
                                                M, N, K, sA, sB, sC, alpha, epi);
    };
    auto gemm_qkv = [&](const __nv_bfloat16* wh, const __nv_bfloat16* wl,
                        const float* bq, const float* bk, const float* bv, int BT) {
        dim3 grid(DD / 128, BT / 128, 3);
        gemm_qkv_kernel<<<grid, 256, 2 * STAGEB>>>(AH, AL, wh, wl, bq, bk, bv, qkv,
                                                   BT, DD, DD, 3 * WSLOT,
                                                   (long long)BT * DD);
    };

    // ---- pre-split ALL weights once, batched over layers ----
    for (int i = 0; i < 4; i++)
        tsplitS(eW[i], WH + wslot(i * 3), WL + wslot(i * 3), DD, DD, WSLOT, WSLOT, LL);
    for (int i = 0; i < 4; i++)
        tsplitS(dW[i], WH + wslot(12 + i * 3), WL + wslot(12 + i * 3), DD, DD, WSLOT, WSLOT, LL);
    tsplitS(pro_w1, WH + wslot(24), WL + wslot(24), DD, DD, WSLOT, WSLOT, 1);
    tsplitS(pro_w2, WH + wslot(25), WL + wslot(25), DD, DD, WSLOT, WSLOT, 1);

    // ---- embedding + score + selection ----
    pe_kernel<<<TT, 256>>>();
    embed_kernel<<<dim3(TT, BB), 128>>>(x, conv_w, ex);
    score_kernel<<<dim3(TT, BB), 256>>>(ex, score);
    select_kernel<<<BB, TT>>>();
    gather_kernel<<<dim3(TU, BB), 256>>>(ex, xe);

    // ---- encoder (Tc = 512) ----
    {
        int Tc = TU, BT = BB * Tc;
        long long sQK = (long long)Tc * DD, sAtt = (long long)Tc * Tc;
        long long regE = (long long)BT * DD;     // region size q|k|v
        float* vptr = qkv + 2 * regE;
        for (int l = 0; l < LL; l++) {
            const float *bq = eBi[0] + l * DD, *bk = eBi[1] + l * DD;
            const float *bv = eBi[2] + l * DD, *bo = eBi[3] + l * DD;
            const __nv_bfloat16 *WoH = WH + wslot(9 + l), *WoL = WL + wslot(9 + l);
            split(xe, AH, AL, regE);
            gemm_qkv(WH + wslot(l), WL + wslot(l), bq, bk, bv, BT);
            split(qkv, AH, AL, 2 * regE);             // q and k -> AH/AL contiguous
            gemm(AH, AL, AH + regE, AL + regE, nullptr, nullptr, att,
                 Tc, Tc, DD, sQK, sQK, sAtt, BB, SCALE, 0);
            softmax_kernel<<<BB * Tc, 256>>>(att, Tc);
            split(att, AH, AL, (long long)BB * Tc * Tc);
            tsplitS(vptr, BH, BL, Tc, DD, sQK, sQK, BB);   // [b][D][Tc]
            gemm(AH, AL, BH, BL, nullptr, xe, t1, Tc, DD, Tc, sAtt, sQK, sQK, BB, 1.f, 0);
            ln_kernel<<<BT, 256>>>(t1, eg + l * DD, ebb + l * DD, t2);
            split(t2, AH, AL, regE);
            gemm(AH, AL, WoH, WoL, bo, t1, xe, BT, DD, DD, 0, 0, 0, 1, 1.f, 0);
        }
        ln_kernel<<<BT, 256>>>(xe, eng, enb, t1);    // ux in t1
    }

    // ---- decoder tokens ----
    tokens_kernel<<<dim3(TT, BB), 256>>>(t1, mask_token, tok);

    // ---- decoder (Tc = 1024), attention maps into d_out ----
    {
        int Tc = TT, BT = BB * Tc;
        long long sQK = (long long)Tc * DD, sAtt = (long long)Tc * Tc;
        long long regD = (long long)BT * DD;
        float* vptr = qkv + 2 * regD;
        for (int l = 0; l < LL; l++) {
            const float *bq = dBi[0] + l * DD, *bk = dBi[1] + l * DD;
            const float *bv = dBi[2] + l * DD, *bo = dBi[3] + l * DD;
            const __nv_bfloat16 *WoH = WH + wslot(12 + 9 + l), *WoL = WL + wslot(12 + 9 + l);
            float* attOut = (float*)d_out + (long long)l * BB * TT * TT;
            split(tok, AH, AL, regD);
            gemm_qkv(WH + wslot(12 + l), WL + wslot(12 + l), bq, bk, bv, BT);
            split(qkv, AH, AL, 2 * regD);             // q and k -> AH/AL
            gemm(AH, AL, AH + regD, AL + regD, nullptr, nullptr, attOut,
                 Tc, Tc, DD, sQK, sQK, sAtt, BB, SCALE, 0);
            softmax_kernel<<<BB * Tc, 256>>>(attOut, Tc);
            split(attOut, AH, AL, (long long)BB * Tc * Tc);
            tsplitS(vptr, BH, BL, Tc, DD, sQK, sQK, BB);   // [b][D][Tc]
            gemm(AH, AL, BH, BL, nullptr, tok, t1, Tc, DD, Tc, sAtt, sQK, sQK, BB, 1.f, 0);
            ln_kernel<<<BT, 256>>>(t1, dg + l * DD, dbb + l * DD, t2);
            split(t2, AH, AL, regD);
            gemm(AH, AL, WoH, WoL, bo, t1, tok, BT, DD, DD, 0, 0, 0, 1, 1.f, 0);
        }
        ln_kernel<<<BB * TT, 256>>>(tok, dng, dnb, t1);   // dx in t1

        // ---- projector: rec = sigmoid(gelu(dx@W1+b1)@W2+b2) ----
        float* rec = (float*)d_out + (long long)LL * BB * TT * TT;
        split(t1, AH, AL, (long long)BB * TT * DD);
        gemm(AH, AL, WH + wslot(24), WL + wslot(24), pro_b1, nullptr, t2,
             BB * TT, DD, DD, 0, 0, 0, 1, 1.f, 1);
        split(t2, AH, AL, (long long)BB * TT * DD);
        gemm(AH, AL, WH + wslot(25), WL + wslot(25), pro_b2, nullptr, rec,
             BB * TT, DD, DD, 0, 0, 0, 1, 1.f, 2);
    }
}

// round 17
// speedup vs baseline: 1.7172x; 1.0170x over previous
#include <cuda_runtime.h>
#include <cuda_bf16.h>
#include <stdint.h>
#include <math.h>

typedef unsigned int u32;

// ---------------- problem constants ----------------
#define BB 8
#define TT 1024
#define CIN 55
#define DD 512
#define LL 3
#define SEQW 10
#define TRR 512          // masked count
#define TU 512           // unmasked count (T - TR)

// ---------------- device scratch ----------------
__device__ float g_pe[TT * DD];
__device__ float g_ex[BB * TT * DD];
__device__ float g_xe[BB * TU * DD];
__device__ float g_qkv[3u * BB * TT * DD];   // q | k | v regions
__device__ float g_att[BB * TU * TU];
__device__ float g_t1[BB * TT * DD];
__device__ float g_tok[BB * TT * DD];
__device__ float g_score[BB * TT];
__device__ int   g_flag[BB * TT];
__device__ int   g_upos[BB * TT];
__device__ int   g_ulist[BB * TU];

// bf16 hi/lo split scratch
__device__ __nv_bfloat16 g_AH[8u*1024*1024];   // A operand (q+k HL, att HL)
__device__ __nv_bfloat16 g_AL[8u*1024*1024];
__device__ __nv_bfloat16 g_BH[8u*1024*512];    // B operand (v^T HL)
__device__ __nv_bfloat16 g_BL[8u*1024*512];
__device__ __nv_bfloat16 g_TH[BB*TT*DD], g_TL[BB*TT*DD];  // ln output HL
// ALL weights pre-split once: 26 slots of 512x512
#define WSLOT (512LL * 512LL)
__device__ __nv_bfloat16 g_WH[26 * 512 * 512];
__device__ __nv_bfloat16 g_WL[26 * 512 * 512];

// ---------------- PE ----------------
__global__ void pe_kernel() {
    int t = blockIdx.x;
    int i = threadIdx.x;                 // 0..255
    float divv = expf((float)(2 * i) * (-9.210340371976184f / (float)DD));
    float ang = (float)t * divv;
    g_pe[t * DD + 2 * i]     = sinf(ang);
    g_pe[t * DD + 2 * i + 1] = cosf(ang);
}

// ---------------- embedding: circular conv1d + PE ----------------
__global__ void embed_kernel(const float* __restrict__ x, const float* __restrict__ cw,
                             float* __restrict__ ex) {
    int t = blockIdx.x, b = blockIdx.y;
    __shared__ float sw[CIN * 3];
    int tid = threadIdx.x;               // 128 threads
    for (int i = tid; i < CIN * 3; i += 128) {
        int c = i / 3, k = i % 3;
        int tt = t + k - 1;
        if (tt < 0) tt += TT;
        if (tt >= TT) tt -= TT;
        sw[i] = x[((long long)b * TT + tt) * CIN + c];
    }
    __syncthreads();
#pragma unroll
    for (int p = 0; p < 4; p++) {
        int d = tid + p * 128;
        const float* w = cw + (long long)d * (CIN * 3);
        float acc = 0.f;
#pragma unroll 15
        for (int i = 0; i < CIN * 3; i++) acc = fmaf(sw[i], w[i], acc);
        ex[((long long)b * TT + t) * DD + d] = acc + g_pe[t * DD + d];
    }
}

// ---------------- windowed mean/var score ----------------
__global__ void score_kernel(const float* __restrict__ ex, float* __restrict__ score) {
    int t = blockIdx.x, b = blockIdx.y;
    int lo = t - (SEQW - 1); if (lo < 0) lo = 0;
    float inv = 1.f / (float)(t + 1 - lo);
    int tid = threadIdx.x;               // 256
    float vs = 0.f, ms = 0.f;
#pragma unroll
    for (int p = 0; p < 2; p++) {
        int d = tid + p * 256;
        float s1 = 0.f, s2 = 0.f;
        for (int w = lo; w <= t; w++) {
            float v = ex[((long long)b * TT + w) * DD + d];
            s1 += v; s2 += v * v;
        }
        float m = s1 * inv, m2 = s2 * inv;
        vs += m2 - m * m;
        ms += m;
    }
    __shared__ float rv[256], rm[256];
    rv[tid] = vs; rm[tid] = ms; __syncthreads();
    for (int s = 128; s > 0; s >>= 1) {
        if (tid < s) { rv[tid] += rv[tid + s]; rm[tid] += rm[tid + s]; }
        __syncthreads();
    }
    if (tid == 0) score[b * TT + t] = rv[0] / rm[0];
}

// ---------------- selection: rank with top_k tie-break ----------------
__global__ void select_kernel() {
    int b = blockIdx.x;
    int t = threadIdx.x;                 // 1024 threads
    __shared__ float ss[TT];
    __shared__ int   sf[TT];
    float myv = g_score[b * TT + t];
    ss[t] = myv;
    __syncthreads();
    int rank = 0;
    for (int i = 0; i < TT; i++) {
        float o = ss[i];
        rank += (o > myv) || (o == myv && i < t);
    }
    int masked = (rank < TRR) ? 1 : 0;
    sf[t] = masked;
    __syncthreads();
    int ucnt = 0;
    for (int i = 0; i < t; i++) ucnt += (sf[i] == 0);
    g_flag[b * TT + t] = masked;
    if (!masked) {
        g_upos[b * TT + t] = ucnt;
        g_ulist[b * TU + ucnt] = t;
    } else {
        g_upos[b * TT + t] = -1;
    }
}

// ---------------- split helpers ----------------
__device__ __forceinline__ void writeHL1(__nv_bfloat16* H, __nv_bfloat16* L,
                                         long long idx, float v) {
    __nv_bfloat16 h = __float2bfloat16(v);
    H[idx] = h;
    L[idx] = __float2bfloat16(v - __bfloat162float(h));
}

// ---------------- gather unmasked tokens ----------------
__global__ void gather_kernel(const float* __restrict__ ex, float* __restrict__ xe) {
    int p = blockIdx.x, b = blockIdx.y;
    int t = g_ulist[b * TU + p];
    const float* src = ex + ((long long)b * TT + t) * DD;
    float* dst = xe + ((long long)b * TU + p) * DD;
    for (int d = threadIdx.x; d < DD; d += 256) dst[d] = src[d];
}

// ---------------- build decoder tokens ----------------
__global__ void tokens_kernel(const float* __restrict__ ux, const float* __restrict__ mtk,
                              float* __restrict__ tok) {
    int t = blockIdx.x, b = blockIdx.y;
    float* dst = tok + ((long long)b * TT + t) * DD;
    if (g_flag[b * TT + t]) {
        for (int d = threadIdx.x; d < 512; d += 256)
            dst[d] = mtk[d] + g_pe[t * DD + d];
    } else {
        int p = g_upos[b * TT + t];
        const float* src = ux + ((long long)b * TU + p) * DD;
        for (int d = threadIdx.x; d < 512; d += 256) dst[d] = src[d];
    }
}

// ================= split / transpose-split prep kernels =================
__global__ void split_kernel(const float* __restrict__ X, __nv_bfloat16* __restrict__ H,
                             __nv_bfloat16* __restrict__ L, int n4) {
    int i = blockIdx.x * blockDim.x + threadIdx.x;
    if (i >= n4) return;
    float4 v = ((const float4*)X)[i];
    __nv_bfloat16 h0 = __float2bfloat16(v.x), h1 = __float2bfloat16(v.y);
    __nv_bfloat16 h2 = __float2bfloat16(v.z), h3 = __float2bfloat16(v.w);
    float r0 = v.x - __bfloat162float(h0), r1 = v.y - __bfloat162float(h1);
    float r2 = v.z - __bfloat162float(h2), r3 = v.w - __bfloat162float(h3);
    __nv_bfloat162* Hp = (__nv_bfloat162*)H;
    __nv_bfloat162* Lp = (__nv_bfloat162*)L;
    Hp[2*i]   = __halves2bfloat162(h0, h1);
    Hp[2*i+1] = __halves2bfloat162(h2, h3);
    Lp[2*i]   = __floats2bfloat162_rn(r0, r1);
    Lp[2*i+1] = __floats2bfloat162_rn(r2, r3);
}

// X: batch b at X + b*sIn, [R][C] fp32 -> H,L at + b*sOut, [C][R] bf16
__global__ void tsplit_kernel(const float* __restrict__ X, __nv_bfloat16* __restrict__ H,
                              __nv_bfloat16* __restrict__ L, int R, int C,
                              long long sIn, long long sOut) {
    __shared__ float tile[32][33];
    int b = blockIdx.z;
    int c0 = blockIdx.x * 32, r0 = blockIdx.y * 32;
    const float* Xb = X + (long long)b * sIn;
    int tx = threadIdx.x, ty = threadIdx.y;   // 32 x 8
#pragma unroll
    for (int i = ty; i < 32; i += 8)
        tile[i][tx] = Xb[(long long)(r0 + i) * C + c0 + tx];
    __syncthreads();
    long long ob = (long long)b * sOut;
#pragma unroll
    for (int i = ty; i < 32; i += 8) {
        float v = tile[tx][i];                // element (r0+tx, c0+i)
        __nv_bfloat16 h = __float2bfloat16(v);
        float rr = v - __bfloat162float(h);
        long long o = ob + (long long)(c0 + i) * R + r0 + tx;
        H[o] = h;
        L[o] = __float2bfloat16(rr);
    }
}

// ================= tensor-core GEMM on pre-split bf16 =================
// EXACT R5 loop: 8 warps, warp tile 64x32, 2-stage cp.async.

#define RSTR 40   // halfwords per smem row (32 data + 8 pad) -> 80B rows
#define PARTB (128 * RSTR * 2)     // bytes per part (10240)
#define STAGEB (4 * PARTB)         // bytes per stage (40960)

__device__ __forceinline__ void cpa(u32 dst, const void* src) {
    asm volatile("cp.async.cg.shared.global [%0], [%1], 16;\n" :: "r"(dst), "l"(src));
}
__device__ __forceinline__ void ldsm4(u32* r, u32 addr) {
    asm volatile("ldmatrix.sync.aligned.m8n8.x4.shared.b16 {%0,%1,%2,%3}, [%4];\n"
        : "=r"(r[0]), "=r"(r[1]), "=r"(r[2]), "=r"(r[3]) : "r"(addr));
}
__device__ __forceinline__ void mma16816(float* d, const u32* a, u32 b0, u32 b1) {
    asm volatile(
        "mma.sync.aligned.m16n8k16.row.col.f32.bf16.bf16.f32 "
        "{%0,%1,%2,%3}, {%4,%5,%6,%7}, {%8,%9}, {%0,%1,%2,%3};\n"
        : "+f"(d[0]), "+f"(d[1]), "+f"(d[2]), "+f"(d[3])
        : "r"(a[0]), "r"(a[1]), "r"(a[2]), "r"(a[3]), "r"(b0), "r"(b1));
}

__device__ __forceinline__ void load_stage(
    u32 sbase, const __nv_bfloat16* Ah, const __nv_bfloat16* Al,
    const __nv_bfloat16* Bh, const __nv_bfloat16* Bl,
    int m0, int n0, int K, int k0, int tid) {
    int r = tid >> 2, c = tid & 3;
    u32 off1 = (u32)(r * RSTR + c * 8) * 2;
    u32 off2 = (u32)((r + 64) * RSTR + c * 8) * 2;
    long long a1 = (long long)(m0 + r) * K + k0 + c * 8;
    long long a2 = a1 + (long long)64 * K;
    long long b1 = (long long)(n0 + r) * K + k0 + c * 8;
    long long b2 = b1 + (long long)64 * K;
    cpa(sbase + off1, Ah + a1);               cpa(sbase + off2, Ah + a2);
    cpa(sbase + PARTB + off1, Al + a1);       cpa(sbase + PARTB + off2, Al + a2);
    cpa(sbase + 2*PARTB + off1, Bh + b1);     cpa(sbase + 2*PARTB + off2, Bh + b2);
    cpa(sbase + 3*PARTB + off1, Bl + b1);     cpa(sbase + 3*PARTB + off2, Bl + b2);
    asm volatile("cp.async.commit_group;\n");
}

// core compute loop shared textually (macro keeps regalloc per-kernel)
#define GEMM_CORE(ACC)                                                                 \
    int nk = K / 32;                                                                   \
    load_stage(smb, Ah, Al, Bh, Bl, m0, n0, K, 0, tid);                                \
    load_stage(smb + STAGEB, Ah, Al, Bh, Bl, m0, n0, K, 32, tid);                      \
    int arow = lane & 15;                                                              \
    int achkbase = lane >> 4;                                                          \
    int brow = (lane & 7) + ((lane & 16) >> 1);                                        \
    int bchkbase = (lane >> 3) & 1;                                                    \
    for (int kt = 0; kt < nk; kt++) {                                                  \
        asm volatile("cp.async.wait_group 1;\n");                                      \
        __syncthreads();                                                               \
        u32 base = smb + (kt & 1) * STAGEB;                                            \
        u32 aH = base, aL = base + PARTB, bH = base + 2*PARTB, bL = base + 3*PARTB;    \
        _Pragma("unroll")                                                              \
        for (int kq = 0; kq < 2; kq++) {                                               \
            u32 ah[4][4], al[4][4];                                                    \
            int achk = kq * 2 + achkbase;                                              \
            _Pragma("unroll")                                                          \
            for (int mf = 0; mf < 4; mf++) {                                           \
                u32 off = (u32)((wm + mf * 16 + arow) * RSTR + achk * 8) * 2;          \
                ldsm4(ah[mf], aH + off);                                               \
                ldsm4(al[mf], aL + off);                                               \
            }                                                                          \
            int bchk = kq * 2 + bchkbase;                                              \
            _Pragma("unroll")                                                          \
            for (int np = 0; np < 2; np++) {                                           \
                u32 off = (u32)((wn + np * 16 + brow) * RSTR + bchk * 8) * 2;          \
                u32 bh[4], bl[4];                                                      \
                ldsm4(bh, bH + off);                                                   \
                ldsm4(bl, bL + off);                                                   \
                _Pragma("unroll")                                                      \
                for (int ni = 0; ni < 2; ni++) {                                       \
                    int nf = np * 2 + ni;                                              \
                    u32 b0h = bh[ni*2], b1h = bh[ni*2+1];                              \
                    u32 b0l = bl[ni*2], b1l = bl[ni*2+1];                              \
                    _Pragma("unroll")                                                  \
                    for (int mf = 0; mf < 4; mf++) {                                   \
                        mma16816(ACC[mf][nf], ah[mf], b0h, b1h);                       \
                        mma16816(ACC[mf][nf], ah[mf], b0l, b1l);                       \
                        mma16816(ACC[mf][nf], al[mf], b0h, b1h);                       \
                    }                                                                  \
                }                                                                      \
            }                                                                          \
        }                                                                              \
        __syncthreads();                                                               \
        if (kt + 2 < nk)                                                               \
            load_stage(smb + (kt & 1) * STAGEB, Ah, Al, Bh, Bl, m0, n0, K,             \
                       (kt + 2) * 32, tid);                                            \
        else                                                                           \
            asm volatile("cp.async.commit_group;\n");                                  \
    }

__global__ __launch_bounds__(256)
void gemm2_kernel(const __nv_bfloat16* __restrict__ Ah, const __nv_bfloat16* __restrict__ Al,
                  const __nv_bfloat16* __restrict__ Bh, const __nv_bfloat16* __restrict__ Bl,
                  const float* __restrict__ bias, const float* __restrict__ resid,
                  float* __restrict__ C, int M, int N, int K,
                  long long sA, long long sB, long long sC,
                  float alpha, int epi) {
    extern __shared__ __nv_bfloat16 smraw[];
    u32 smb = (u32)__cvta_generic_to_shared(smraw);

    int bz = blockIdx.z;
    Ah += (long long)bz * sA; Al += (long long)bz * sA;
    Bh += (long long)bz * sB; Bl += (long long)bz * sB;
    C  += (long long)bz * sC;
    const float* R = resid ? resid + (long long)bz * sC : nullptr;

    int m0 = blockIdx.y * 128, n0 = blockIdx.x * 128;
    int tid = threadIdx.x, lane = tid & 31, wid = tid >> 5;
    int wm = (wid & 1) * 64, wn = (wid >> 1) * 32;
    int g = lane >> 2, t4 = lane & 3;

    float acc[4][4][4];
#pragma unroll
    for (int i = 0; i < 4; i++)
#pragma unroll
        for (int j = 0; j < 4; j++)
#pragma unroll
            for (int q = 0; q < 4; q++) acc[i][j][q] = 0.f;

    GEMM_CORE(acc)

    // ---- epilogue ----
#pragma unroll
    for (int mf = 0; mf < 4; mf++) {
        int r0 = m0 + wm + mf * 16 + g;
#pragma unroll
        for (int nf = 0; nf < 4; nf++) {
            int cc = n0 + wn + nf * 8 + t4 * 2;
#pragma unroll
            for (int half = 0; half < 2; half++) {
                int r = r0 + half * 8;
                float v0 = acc[mf][nf][half * 2 + 0] * alpha;
                float v1 = acc[mf][nf][half * 2 + 1] * alpha;
                if (bias) { v0 += bias[cc]; v1 += bias[cc + 1]; }
                if (R) {
                    v0 += R[(long long)r * N + cc];
                    v1 += R[(long long)r * N + cc + 1];
                }
                if (epi == 1) {
                    v0 = 0.5f * v0 * (1.f + erff(v0 * 0.7071067811865475f));
                    v1 = 0.5f * v1 * (1.f + erff(v1 * 0.7071067811865475f));
                } else if (epi == 2) {
                    v0 = 1.f / (1.f + __expf(-v0));
                    v1 = 1.f / (1.f + __expf(-v1));
                }
                *(float2*)(C + (long long)r * N + cc) = make_float2(v0, v1);
            }
        }
    }
}

// ---- batched QKV projection: grid.z selects q/k/v ----
__global__ __launch_bounds__(256)
void gemm_qkv_kernel(const __nv_bfloat16* __restrict__ Ah, const __nv_bfloat16* __restrict__ Al,
                     const __nv_bfloat16* __restrict__ Bh, const __nv_bfloat16* __restrict__ Bl,
                     const float* __restrict__ b0p, const float* __restrict__ b1p,
                     const float* __restrict__ b2p,
                     float* __restrict__ C, int M, int N, int K,
                     long long sB, long long sC) {
    extern __shared__ __nv_bfloat16 smraw[];
    u32 smb = (u32)__cvta_generic_to_shared(smraw);

    int bz = blockIdx.z;
    Bh += (long long)bz * sB; Bl += (long long)bz * sB;
    C  += (long long)bz * sC;
    const float* bias = (bz == 0) ? b0p : (bz == 1) ? b1p : b2p;

    int m0 = blockIdx.y * 128, n0 = blockIdx.x * 128;
    int tid = threadIdx.x, lane = tid & 31, wid = tid >> 5;
    int wm = (wid & 1) * 64, wn = (wid >> 1) * 32;
    int g = lane >> 2, t4 = lane & 3;

    float acc[4][4][4];
#pragma unroll
    for (int i = 0; i < 4; i++)
#pragma unroll
        for (int j = 0; j < 4; j++)
#pragma unroll
            for (int q = 0; q < 4; q++) acc[i][j][q] = 0.f;

    GEMM_CORE(acc)

#pragma unroll
    for (int mf = 0; mf < 4; mf++) {
        int r0 = m0 + wm + mf * 16 + g;
#pragma unroll
        for (int nf = 0; nf < 4; nf++) {
            int cc = n0 + wn + nf * 8 + t4 * 2;
#pragma unroll
            for (int half = 0; half < 2; half++) {
                int r = r0 + half * 8;
                float v0 = acc[mf][nf][half * 2 + 0] + bias[cc];
                float v1 = acc[mf][nf][half * 2 + 1] + bias[cc + 1];
                *(float2*)(C + (long long)r * N + cc) = make_float2(v0, v1);
            }
        }
    }
}

// ---------------- softmax with fused hi/lo emit ----------------
__global__ void softmax_split_kernel(float* __restrict__ S,
                                     __nv_bfloat16* __restrict__ H,
                                     __nv_bfloat16* __restrict__ L, int Nc) {
    long long row = blockIdx.x;
    float* p = S + row * Nc;
    __shared__ float red[256];
    int tid = threadIdx.x;
    float mx = -1e30f;
    for (int i = tid; i < Nc; i += 256) mx = fmaxf(mx, p[i]);
    red[tid] = mx; __syncthreads();
    for (int s = 128; s > 0; s >>= 1) { if (tid < s) red[tid] = fmaxf(red[tid], red[tid + s]); __syncthreads(); }
    mx = red[0]; __syncthreads();
    float sum = 0.f;
    for (int i = tid; i < Nc; i += 256) { float e = __expf(p[i] - mx); p[i] = e; sum += e; }
    red[tid] = sum; __syncthreads();
    for (int s = 128; s > 0; s >>= 1) { if (tid < s) red[tid] += red[tid + s]; __syncthreads(); }
    float inv = 1.f / red[0];
    long long ro = row * Nc;
    for (int i = tid; i < Nc; i += 256) {
        float e = p[i] * inv;
        p[i] = e;
        writeHL1(H, L, ro + i, e);
    }
}

// ---------------- layer norm -> fp32 ----------------
__global__ void ln_kernel(const float* __restrict__ X, const float* __restrict__ g,
                          const float* __restrict__ b, float* __restrict__ Y) {
    long long row = blockIdx.x;
    const float* x = X + row * DD;
    float* y = Y + row * DD;
    __shared__ float red[256];
    int tid = threadIdx.x;
    float v0 = x[tid], v1 = x[tid + 256];
    red[tid] = v0 + v1; __syncthreads();
    for (int s = 128; s > 0; s >>= 1) { if (tid < s) red[tid] += red[tid + s]; __syncthreads(); }
    float mu = red[0] * (1.f / (float)DD); __syncthreads();
    float d0 = v0 - mu, d1 = v1 - mu;
    red[tid] = d0 * d0 + d1 * d1; __syncthreads();
    for (int s = 128; s > 0; s >>= 1) { if (tid < s) red[tid] += red[tid + s]; __syncthreads(); }
    float inv = rsqrtf(red[0] * (1.f / (float)DD) + 1e-5f);
    y[tid]       = d0 * inv * g[tid] + b[tid];
    y[tid + 256] = d1 * inv * g[tid + 256] + b[tid + 256];
}

// ---------------- layer norm with fused hi/lo emit ----------------
__global__ void ln_split_kernel(const float* __restrict__ X, const float* __restrict__ g,
                                const float* __restrict__ b,
                                __nv_bfloat16* __restrict__ H, __nv_bfloat16* __restrict__ L) {
    long long row = blockIdx.x;
    const float* x = X + row * DD;
    __shared__ float red[256];
    int tid = threadIdx.x;
    float v0 = x[tid], v1 = x[tid + 256];
    red[tid] = v0 + v1; __syncthreads();
    for (int s = 128; s > 0; s >>= 1) { if (tid < s) red[tid] += red[tid + s]; __syncthreads(); }
    float mu = red[0] * (1.f / (float)DD); __syncthreads();
    float d0 = v0 - mu, d1 = v1 - mu;
    red[tid] = d0 * d0 + d1 * d1; __syncthreads();
    for (int s = 128; s > 0; s >>= 1) { if (tid < s) red[tid] += red[tid + s]; __syncthreads(); }
    float inv = rsqrtf(red[0] * (1.f / (float)DD) + 1e-5f);
    long long ro = row * DD;
    writeHL1(H, L, ro + tid,       d0 * inv * g[tid] + b[tid]);
    writeHL1(H, L, ro + tid + 256, d1 * inv * g[tid + 256] + b[tid + 256]);
}

// ---------------- host orchestration ----------------
extern "C" void kernel_launch(void* const* d_in, const int* in_sizes, int n_in,
                              void* d_out, int out_size) {
    float *ex, *xe, *qkv, *att, *t1, *tok, *score;
    cudaGetSymbolAddress((void**)&ex,  g_ex);
    cudaGetSymbolAddress((void**)&xe,  g_xe);
    cudaGetSymbolAddress((void**)&qkv, g_qkv);
    cudaGetSymbolAddress((void**)&att, g_att);
    cudaGetSymbolAddress((void**)&t1,  g_t1);
    cudaGetSymbolAddress((void**)&tok, g_tok);
    cudaGetSymbolAddress((void**)&score, g_score);
    __nv_bfloat16 *AH, *AL, *BH, *BL, *TH, *TL, *WH, *WL;
    cudaGetSymbolAddress((void**)&AH, g_AH);
    cudaGetSymbolAddress((void**)&AL, g_AL);
    cudaGetSymbolAddress((void**)&BH, g_BH);
    cudaGetSymbolAddress((void**)&BL, g_BL);
    cudaGetSymbolAddress((void**)&TH, g_TH);
    cudaGetSymbolAddress((void**)&TL, g_TL);
    cudaGetSymbolAddress((void**)&WH, g_WH);
    cudaGetSymbolAddress((void**)&WL, g_WL);

    static int smem_set = 0;
    if (!smem_set) {
        cudaFuncSetAttribute(gemm2_kernel, cudaFuncAttributeMaxDynamicSharedMemorySize, 2 * STAGEB);
        cudaFuncSetAttribute(gemm_qkv_kernel, cudaFuncAttributeMaxDynamicSharedMemorySize, 2 * STAGEB);
        smem_set = 1;
    }

    const float* in[31];
    for (int i = 0; i < 31 && i < n_in; i++) in[i] = (const float*)d_in[i];

    const float *x = in[0], *conv_w = in[1], *mask_token = in[2];
    const float *pro_w1, *pro_b1, *pro_w2, *pro_b2;
    const float *eW[4], *eBi[4], *eg, *ebb, *eng, *enb;
    const float *dW[4], *dBi[4], *dg, *dbb, *dng, *dnb;

    bool sig = (in_sizes[3] == LL * DD * DD);
    if (sig) {
        eW[0]=in[3];  eBi[0]=in[4];  eW[1]=in[5];  eBi[1]=in[6];
        eW[2]=in[7];  eBi[2]=in[8];  eW[3]=in[9];  eBi[3]=in[10];
        eg=in[11]; ebb=in[12]; eng=in[13]; enb=in[14];
        dW[0]=in[15]; dBi[0]=in[16]; dW[1]=in[17]; dBi[1]=in[18];
        dW[2]=in[19]; dBi[2]=in[20]; dW[3]=in[21]; dBi[3]=in[22];
        dg=in[23]; dbb=in[24]; dng=in[25]; dnb=in[26];
        pro_w1=in[27]; pro_b1=in[28]; pro_w2=in[29]; pro_b2=in[30];
    } else {
        pro_w1=in[3]; pro_b1=in[4]; pro_w2=in[5]; pro_b2=in[6];
        eW[0]=in[7];  eW[1]=in[8];  eW[2]=in[9];  eW[3]=in[10];
        eBi[0]=in[11]; eBi[1]=in[12]; eBi[2]=in[13]; eBi[3]=in[14];
        eg=in[15]; ebb=in[16]; eng=in[17]; enb=in[18];
        dW[0]=in[19]; dW[1]=in[20]; dW[2]=in[21]; dW[3]=in[22];
        dBi[0]=in[23]; dBi[1]=in[24]; dBi[2]=in[25]; dBi[3]=in[26];
        dg=in[27]; dbb=in[28]; dng=in[29]; dnb=in[30];
    }

    const float SCALE = 0.044194173824159216f;  // 1/sqrt(512)

    auto wslot = [&](int s) { return (long long)s * WSLOT; };

    auto split = [&](const float* X, __nv_bfloat16* H, __nv_bfloat16* L, long long n) {
        int n4 = (int)(n / 4);
        split_kernel<<<(n4 + 255) / 256, 256>>>(X, H, L, n4);
    };
    auto tsplitS = [&](const float* X, __nv_bfloat16* H, __nv_bfloat16* L,
                       int R, int C, long long sIn, long long sOut, int nb) {
        tsplit_kernel<<<dim3(C / 32, R / 32, nb), dim3(32, 8)>>>(X, H, L, R, C, sIn, sOut);
    };
    auto gemm = [&](const __nv_bfloat16* ah, const __nv_bfloat16* al,
                    const __nv_bfloat16* bh, const __nv_bfloat16* bl,
                    const float* bias, const float* resid, float* C,
                    int M, int N, int K, long long sA, long long sB, long long sC,
                    int nb, float alpha, int epi) {
        dim3 grid(N / 128, M / 128, nb);
        gemm2_kernel<<<grid, 256, 2 * STAGEB>>>(ah, al, bh, bl, bias, resid, C,
                                                M, N, K, sA, sB, sC, alpha, epi);
    };
    auto gemm_qkv = [&](const __nv_bfloat16* wh, const __nv_bfloat16* wl,
                        const float* bq, const float* bk, const float* bv, int BT) {
        dim3 grid(DD / 128, BT / 128, 3);
        gemm_qkv_kernel<<<grid, 256, 2 * STAGEB>>>(AH, AL, wh, wl, bq, bk, bv, qkv,
                                                   BT, DD, DD, 3 * WSLOT,
                                                   (long long)BT * DD);
    };

    // ---- pre-split ALL weights once, batched over layers ----
    for (int i = 0; i < 4; i++)
        tsplitS(eW[i], WH + wslot(i * 3), WL + wslot(i * 3), DD, DD, WSLOT, WSLOT, LL);
    for (int i = 0; i < 4; i++)
        tsplitS(dW[i], WH + wslot(12 + i * 3), WL + wslot(12 + i * 3), DD, DD, WSLOT, WSLOT, LL);
    tsplitS(pro_w1, WH + wslot(24), WL + wslot(24), DD, DD, WSLOT, WSLOT, 1);
    tsplitS(pro_w2, WH + wslot(25), WL + wslot(25), DD, DD, WSLOT, WSLOT, 1);

    // ---- embedding + score + selection ----
    pe_kernel<<<TT, 256>>>();
    embed_kernel<<<dim3(TT, BB), 128>>>(x, conv_w, ex);
    score_kernel<<<dim3(TT, BB), 256>>>(ex, score);
    select_kernel<<<BB, TT>>>();
    gather_kernel<<<dim3(TU, BB), 256>>>(ex, xe);

    // ---- encoder (Tc = 512) ----
    {
        int Tc = TU, BT = BB * Tc;
        long long sQK = (long long)Tc * DD, sAtt = (long long)Tc * Tc;
        long long regE = (long long)BT * DD;
        float* vptr = qkv + 2 * regE;
        for (int l = 0; l < LL; l++) {
            const float *bq = eBi[0] + l * DD, *bk = eBi[1] + l * DD;
            const float *bv = eBi[2] + l * DD, *bo = eBi[3] + l * DD;
            const __nv_bfloat16 *WoH = WH + wslot(9 + l), *WoL = WL + wslot(9 + l);
            split(xe, AH, AL, regE);
            gemm_qkv(WH + wslot(l), WL + wslot(l), bq, bk, bv, BT);
            split(qkv, AH, AL, 2 * regE);             // q and k -> AH/AL contiguous
            gemm(AH, AL, AH + regE, AL + regE, nullptr, nullptr, att,
                 Tc, Tc, DD, sQK, sQK, sAtt, BB, SCALE, 0);
            // softmax emits probs (fp32, unused afterwards) + hi/lo into AH/AL
            softmax_split_kernel<<<BB * Tc, 256>>>(att, AH, AL, Tc);
            tsplitS(vptr, BH, BL, Tc, DD, sQK, sQK, BB);   // [b][D][Tc]
            gemm(AH, AL, BH, BL, nullptr, xe, t1, Tc, DD, Tc, sAtt, sQK, sQK, BB, 1.f, 0);
            // layernorm emits hi/lo into TH/TL for the Wo GEMM
            ln_split_kernel<<<BT, 256>>>(t1, eg + l * DD, ebb + l * DD, TH, TL);
            gemm(TH, TL, WoH, WoL, bo, t1, xe, BT, DD, DD, 0, 0, 0, 1, 1.f, 0);
        }
        ln_kernel<<<BT, 256>>>(xe, eng, enb, t1);    // ux in t1
    }

    // ---- decoder tokens ----
    tokens_kernel<<<dim3(TT, BB), 256>>>(t1, mask_token, tok);

    // ---- decoder (Tc = 1024), attention maps into d_out ----
    {
        int Tc = TT, BT = BB * Tc;
        long long sQK = (long long)Tc * DD, sAtt = (long long)Tc * Tc;
        long long regD = (long long)BT * DD;
        float* vptr = qkv + 2 * regD;
        for (int l = 0; l < LL; l++) {
            const float *bq = dBi[0] + l * DD, *bk = dBi[1] + l * DD;
            const float *bv = dBi[2] + l * DD, *bo = dBi[3] + l * DD;
            const __nv_bfloat16 *WoH = WH + wslot(12 + 9 + l), *WoL = WL + wslot(12 + 9 + l);
            float* attOut = (float*)d_out + (long long)l * BB * TT * TT;
            split(tok, AH, AL, regD);
            gemm_qkv(WH + wslot(12 + l), WL + wslot(12 + l), bq, bk, bv, BT);
            split(qkv, AH, AL, 2 * regD);             // q and k -> AH/AL
            gemm(AH, AL, AH + regD, AL + regD, nullptr, nullptr, attOut,
                 Tc, Tc, DD, sQK, sQK, sAtt, BB, SCALE, 0);
            softmax_split_kernel<<<BB * Tc, 256>>>(attOut, AH, AL, Tc);
            tsplitS(vptr, BH, BL, Tc, DD, sQK, sQK, BB);   // [b][D][Tc]
            gemm(AH, AL, BH, BL, nullptr, tok, t1, Tc, DD, Tc, sAtt, sQK, sQK, BB, 1.f, 0);
            ln_split_kernel<<<BT, 256>>>(t1, dg + l * DD, dbb + l * DD, TH, TL);
            gemm(TH, TL, WoH, WoL, bo, t1, tok, BT, DD, DD, 0, 0, 0, 1, 1.f, 0);
        }
        ln_split_kernel<<<BB * TT, 256>>>(tok, dng, dnb, TH, TL);   // dx hi/lo

        // ---- projector: rec = sigmoid(gelu(dx@W1+b1)@W2+b2) ----
        float* rec = (float*)d_out + (long long)LL * BB * TT * TT;
        gemm(TH, TL, WH + wslot(24), WL + wslot(24), pro_b1, nullptr, t1,
             BB * TT, DD, DD, 0, 0, 0, 1, 1.f, 1);
        split(t1, AH, AL, (long long)BB * TT * DD);
        gemm(AH, AL, WH + wslot(25), WL + wslot(25), pro_b2, nullptr, rec,
             BB * TT, DD, DD, 0, 0, 0, 1, 1.f, 2);
    }
}